// round 1
// baseline (speedup 1.0000x reference)
#include <cuda_runtime.h>
#include <math.h>

#define BB   4
#define SS   512
#define DMM  768
#define LLN  2
#define DII  1536
#define DSS  16
#define KKC  4
#define DTRR 48
#define RTOT (BB*SS)   // 2048
#define DBCW (DTRR + 2*DSS)  // 80

// -------------------- scratch (device globals; no allocs) --------------------
__device__ float g_h    [RTOT*DMM];
__device__ float g_xln  [RTOT*DMM];
__device__ float g_xz   [RTOT*2*DII];
__device__ float g_xc   [RTOT*DII];
__device__ float g_dbc  [RTOT*DBCW];
__device__ float g_delta[RTOT*DII];
__device__ float g_y    [RTOT*DII];
__device__ float g_rowdot[RTOT];

// -------------------- embed: h = x*w_in + b_in + pe --------------------
__global__ void embed_kernel(const float* __restrict__ x, const float* __restrict__ w_in,
                             const float* __restrict__ b_in, const float* __restrict__ pe,
                             float* __restrict__ h) {
    int idx = blockIdx.x * blockDim.x + threadIdx.x;
    if (idx >= RTOT*DMM) return;
    int r = idx / DMM;
    int d = idx - r*DMM;
    int s = r & (SS-1);
    h[idx] = x[r]*w_in[d] + b_in[d] + pe[s*DMM + d];
}

// -------------------- layernorm (row = 768) --------------------
__global__ __launch_bounds__(256) void ln_kernel(const float* __restrict__ x,
                                                 const float* __restrict__ w,
                                                 const float* __restrict__ b,
                                                 float* __restrict__ y) {
    int row = blockIdx.x;
    const float* xr = x + (size_t)row*DMM;
    float v[3];
    float s = 0.f, sq = 0.f;
#pragma unroll
    for (int i = 0; i < 3; i++) {
        v[i] = xr[threadIdx.x + 256*i];
        s  += v[i];
        sq += v[i]*v[i];
    }
    __shared__ float sms[8], smq[8];
    __shared__ float mu_s, rs_s;
#pragma unroll
    for (int o = 16; o > 0; o >>= 1) {
        s  += __shfl_xor_sync(0xffffffffu, s,  o);
        sq += __shfl_xor_sync(0xffffffffu, sq, o);
    }
    int lane = threadIdx.x & 31, wid = threadIdx.x >> 5;
    if (lane == 0) { sms[wid] = s; smq[wid] = sq; }
    __syncthreads();
    if (threadIdx.x == 0) {
        float S = 0.f, Q = 0.f;
        for (int i = 0; i < 8; i++) { S += sms[i]; Q += smq[i]; }
        float mu = S * (1.0f/DMM);
        float var = Q * (1.0f/DMM) - mu*mu;
        mu_s = mu;
        rs_s = rsqrtf(var + 1e-5f);
    }
    __syncthreads();
    float mu = mu_s, rs = rs_s;
    float* yr = y + (size_t)row*DMM;
#pragma unroll
    for (int i = 0; i < 3; i++) {
        int d = threadIdx.x + 256*i;
        yr[d] = (v[i]-mu)*rs*w[d] + b[d];
    }
}

// -------------------- generic GEMM: C[M,N] = act(A[M,K] * B[N,K]^T + bias) (+res) ------
// ACT: 0 none, 1 gelu(exact), 2 softplus
template<int ACT, bool HAS_BIAS, bool HAS_RES>
__global__ __launch_bounds__(256) void gemm_kernel(
    const float* __restrict__ A, int lda,
    const float* __restrict__ Bw,                 // (N, Kd) row-major, ldb = Kd
    const float* __restrict__ bias,
    const float* __restrict__ res,
    float* __restrict__ C, int ldc,
    int M, int N, int Kd)
{
    const int BM = 128, BN = 64, BK = 16;
    __shared__ float As[BK][BM+4];
    __shared__ float Bs[BK][BN+4];
    int tid = threadIdx.x;
    int tx = tid & 15, ty = tid >> 4;
    int m0 = blockIdx.y * BM;
    int n0 = blockIdx.x * BN;

    float acc[8][4];
#pragma unroll
    for (int i = 0; i < 8; i++)
#pragma unroll
        for (int j = 0; j < 4; j++) acc[i][j] = 0.f;

    for (int k0 = 0; k0 < Kd; k0 += BK) {
        // A tile: 128x16 = 512 float4, 2 per thread
#pragma unroll
        for (int q = 0; q < 2; q++) {
            int f = tid*2 + q;           // 0..511
            int m = f >> 2;              // 0..127
            int kv = (f & 3) * 4;        // 0,4,8,12
            float4 vv = *reinterpret_cast<const float4*>(A + (size_t)(m0+m)*lda + k0 + kv);
            As[kv+0][m] = vv.x; As[kv+1][m] = vv.y; As[kv+2][m] = vv.z; As[kv+3][m] = vv.w;
        }
        // B tile: 64x16 = 256 float4, 1 per thread (guard N)
        {
            int f = tid;
            int n = f >> 2;
            int kv = (f & 3) * 4;
            float4 vv = make_float4(0.f,0.f,0.f,0.f);
            if (n0 + n < N)
                vv = *reinterpret_cast<const float4*>(Bw + (size_t)(n0+n)*Kd + k0 + kv);
            Bs[kv+0][n] = vv.x; Bs[kv+1][n] = vv.y; Bs[kv+2][n] = vv.z; Bs[kv+3][n] = vv.w;
        }
        __syncthreads();
#pragma unroll
        for (int k = 0; k < BK; k++) {
            float4 a0 = *reinterpret_cast<const float4*>(&As[k][ty*8]);
            float4 a1 = *reinterpret_cast<const float4*>(&As[k][ty*8+4]);
            float4 b0 = *reinterpret_cast<const float4*>(&Bs[k][tx*4]);
            float am[8] = {a0.x,a0.y,a0.z,a0.w,a1.x,a1.y,a1.z,a1.w};
            float bn[4] = {b0.x,b0.y,b0.z,b0.w};
#pragma unroll
            for (int i = 0; i < 8; i++)
#pragma unroll
                for (int j = 0; j < 4; j++)
                    acc[i][j] = fmaf(am[i], bn[j], acc[i][j]);
        }
        __syncthreads();
    }

#pragma unroll
    for (int i = 0; i < 8; i++) {
        int m = m0 + ty*8 + i;
#pragma unroll
        for (int j = 0; j < 4; j++) {
            int n = n0 + tx*4 + j;
            if (n < N) {
                float v = acc[i][j];
                if (HAS_BIAS) v += bias[n];
                if (ACT == 1) v = 0.5f * v * (1.0f + erff(v * 0.70710678118654752f));
                else if (ACT == 2) v = (v > 20.f) ? v : log1pf(__expf(v));
                if (HAS_RES) v += res[(size_t)m*ldc + n];
                C[(size_t)m*ldc + n] = v;
            }
        }
    }
}

// -------------------- causal depthwise conv (K=4) + silu --------------------
__global__ void conv_silu_kernel(const float* __restrict__ xz,
                                 const float* __restrict__ cw,
                                 const float* __restrict__ cb,
                                 float* __restrict__ xc) {
    int idx = blockIdx.x * blockDim.x + threadIdx.x;
    if (idx >= RTOT*DII) return;
    int d = idx % DII;
    int r = idx / DII;
    int s = r & (SS-1);
    float acc = cb[d];
#pragma unroll
    for (int k = 0; k < KKC; k++) {
        int sk = s - (KKC-1) + k;
        if (sk >= 0)
            acc = fmaf(xz[(size_t)(r + sk - s)*(2*DII) + d], cw[d*KKC + k], acc);
    }
    float sg = 1.f / (1.f + __expf(-acc));
    xc[idx] = acc * sg;
}

// -------------------- selective scan --------------------
// one thread per (b,d); B/C staged in smem; power-trick for exp(delta*A_i)
__global__ __launch_bounds__(256) void scan_kernel(
    const float* __restrict__ delta, const float* __restrict__ dbc,
    const float* __restrict__ xc,    const float* __restrict__ xz,
    const float* __restrict__ A_log, const float* __restrict__ Dw,
    float* __restrict__ y)
{
    int b = blockIdx.y;
    int d = blockIdx.x*256 + threadIdx.x;

    float Av[DSS];
#pragma unroll
    for (int i = 0; i < DSS; i++) Av[i] = -__expf(A_log[d*DSS + i]);
    float a0 = Av[0];
    bool fast = true;
#pragma unroll
    for (int i = 0; i < DSS; i++)
        if (fabsf(Av[i] - (float)(i+1)*a0) > 1e-4f*fabsf(Av[i]) + 1e-6f) fast = false;

    float Dd = Dw[d];
    float h[DSS];
#pragma unroll
    for (int i = 0; i < DSS; i++) h[i] = 0.f;

    __shared__ float sBC[32][33];   // [step][0..15]=B, [16..31]=C (pad avoids store conflicts)

    for (int s0 = 0; s0 < SS; s0 += 32) {
        __syncthreads();
#pragma unroll
        for (int q = 0; q < 4; q++) {
            int f = threadIdx.x + q*256;
            int j = f >> 5, c = f & 31;
            sBC[j][c] = dbc[(size_t)(b*SS + s0 + j)*DBCW + DTRR + c];
        }
        __syncthreads();
        for (int j = 0; j < 32; j++) {
            size_t r = (size_t)(b*SS + s0 + j);
            float dl = delta[r*DII + d];
            float u  = xc[r*DII + d];
            float du = dl*u;
            float yacc = 0.f;
            if (fast) {
                float t = __expf(dl*a0);
                float p = 1.f;
#pragma unroll
                for (int i = 0; i < DSS; i++) {
                    p *= t;                               // p = t^(i+1) = exp(dl*A_i)
                    h[i] = fmaf(h[i], p, du*sBC[j][i]);
                    yacc = fmaf(h[i], sBC[j][16+i], yacc);
                }
            } else {
#pragma unroll
                for (int i = 0; i < DSS; i++) {
                    float e = __expf(dl*Av[i]);
                    h[i] = fmaf(h[i], e, du*sBC[j][i]);
                    yacc = fmaf(h[i], sBC[j][16+i], yacc);
                }
            }
            float ys = yacc + u*Dd;
            float z  = xz[r*(2*DII) + DII + d];
            float sg = 1.f / (1.f + __expf(-z));
            y[r*DII + d] = ys * (z*sg);
        }
    }
}

// -------------------- final LN + dot(w_head) per row --------------------
__global__ __launch_bounds__(256) void headrow_kernel(const float* __restrict__ x,
                                                      const float* __restrict__ w,
                                                      const float* __restrict__ b,
                                                      const float* __restrict__ wh,
                                                      float* __restrict__ rowdot) {
    int row = blockIdx.x;
    const float* xr = x + (size_t)row*DMM;
    float v[3];
    float s = 0.f, sq = 0.f;
#pragma unroll
    for (int i = 0; i < 3; i++) {
        v[i] = xr[threadIdx.x + 256*i];
        s += v[i]; sq += v[i]*v[i];
    }
    __shared__ float sms[8], smq[8];
    __shared__ float mu_s, rs_s;
#pragma unroll
    for (int o = 16; o > 0; o >>= 1) {
        s  += __shfl_xor_sync(0xffffffffu, s,  o);
        sq += __shfl_xor_sync(0xffffffffu, sq, o);
    }
    int lane = threadIdx.x & 31, wid = threadIdx.x >> 5;
    if (lane == 0) { sms[wid] = s; smq[wid] = sq; }
    __syncthreads();
    if (threadIdx.x == 0) {
        float S = 0.f, Q = 0.f;
        for (int i = 0; i < 8; i++) { S += sms[i]; Q += smq[i]; }
        float mu = S * (1.0f/DMM);
        float var = Q * (1.0f/DMM) - mu*mu;
        mu_s = mu; rs_s = rsqrtf(var + 1e-5f);
    }
    __syncthreads();
    float mu = mu_s, rs = rs_s;
    float p = 0.f;
#pragma unroll
    for (int i = 0; i < 3; i++) {
        int d = threadIdx.x + 256*i;
        p = fmaf((v[i]-mu)*rs*w[d] + b[d], wh[d], p);
    }
#pragma unroll
    for (int o = 16; o > 0; o >>= 1) p += __shfl_xor_sync(0xffffffffu, p, o);
    __syncthreads();
    if (lane == 0) sms[wid] = p;
    __syncthreads();
    if (threadIdx.x == 0) {
        float S = 0.f;
        for (int i = 0; i < 8; i++) S += sms[i];
        rowdot[row] = S;
    }
}

__global__ __launch_bounds__(256) void final_kernel(const float* __restrict__ rowdot,
                                                    const float* __restrict__ b_head,
                                                    float* __restrict__ out) {
    int b = blockIdx.x;
    float s = 0.f;
    for (int j = threadIdx.x; j < SS; j += 256) s += rowdot[b*SS + j];
    __shared__ float sms[8];
#pragma unroll
    for (int o = 16; o > 0; o >>= 1) s += __shfl_xor_sync(0xffffffffu, s, o);
    int lane = threadIdx.x & 31, wid = threadIdx.x >> 5;
    if (lane == 0) sms[wid] = s;
    __syncthreads();
    if (threadIdx.x == 0) {
        float S = 0.f;
        for (int i = 0; i < 8; i++) S += sms[i];
        out[b] = b_head[0] + S * (1.0f/SS);
    }
}

// -------------------- launch --------------------
extern "C" void kernel_launch(void* const* d_in, const int* in_sizes, int n_in,
                              void* d_out, int out_size) {
    const float* x        = (const float*)d_in[0];
    const float* w_in     = (const float*)d_in[1];
    const float* b_in     = (const float*)d_in[2];
    const float* pe       = (const float*)d_in[3];
    const float* ln1_w    = (const float*)d_in[4];
    const float* ln1_b    = (const float*)d_in[5];
    const float* w_inproj = (const float*)d_in[6];
    const float* conv_w   = (const float*)d_in[7];
    const float* conv_b   = (const float*)d_in[8];
    const float* w_xproj  = (const float*)d_in[9];
    const float* w_dt     = (const float*)d_in[10];
    const float* b_dt     = (const float*)d_in[11];
    const float* A_log    = (const float*)d_in[12];
    const float* Dmat     = (const float*)d_in[13];
    const float* w_outproj= (const float*)d_in[14];
    const float* ln2_w    = (const float*)d_in[15];
    const float* ln2_b    = (const float*)d_in[16];
    const float* ff_w1    = (const float*)d_in[17];
    const float* ff_b1    = (const float*)d_in[18];
    const float* ff_w2    = (const float*)d_in[19];
    const float* ff_b2    = (const float*)d_in[20];
    const float* lnf_w    = (const float*)d_in[21];
    const float* lnf_b    = (const float*)d_in[22];
    const float* w_head   = (const float*)d_in[23];
    const float* b_head   = (const float*)d_in[24];
    float* out = (float*)d_out;

    float *h, *xln, *xz, *xc, *dbc, *delta, *y, *rowdot;
    cudaGetSymbolAddress((void**)&h,     g_h);
    cudaGetSymbolAddress((void**)&xln,   g_xln);
    cudaGetSymbolAddress((void**)&xz,    g_xz);
    cudaGetSymbolAddress((void**)&xc,    g_xc);
    cudaGetSymbolAddress((void**)&dbc,   g_dbc);
    cudaGetSymbolAddress((void**)&delta, g_delta);
    cudaGetSymbolAddress((void**)&y,     g_y);
    cudaGetSymbolAddress((void**)&rowdot,g_rowdot);

    const int GM = RTOT/128;  // 16 row-blocks

    embed_kernel<<<(RTOT*DMM + 255)/256, 256>>>(x, w_in, b_in, pe, h);

    for (int l = 0; l < LLN; l++) {
        // ln1
        ln_kernel<<<RTOT, 256>>>(h, ln1_w + l*DMM, ln1_b + l*DMM, xln);
        // inproj: xz[2048,3072] = xln @ w_inproj^T
        gemm_kernel<0,false,false><<<dim3((2*DII)/64, GM), 256>>>(
            xln, DMM, w_inproj + (size_t)l*2*DII*DMM, nullptr, nullptr,
            xz, 2*DII, RTOT, 2*DII, DMM);
        // conv + silu on xm half
        conv_silu_kernel<<<(RTOT*DII + 255)/256, 256>>>(
            xz, conv_w + (size_t)l*DII*KKC, conv_b + l*DII, xc);
        // xproj: dbc[2048,80] = xc @ w_xproj^T
        gemm_kernel<0,false,false><<<dim3((DBCW + 63)/64, GM), 256>>>(
            xc, DII, w_xproj + (size_t)l*DBCW*DII, nullptr, nullptr,
            dbc, DBCW, RTOT, DBCW, DII);
        // delta = softplus(dbc[:, :48] @ w_dt^T + b_dt)
        gemm_kernel<2,true,false><<<dim3(DII/64, GM), 256>>>(
            dbc, DBCW, w_dt + (size_t)l*DII*DTRR, b_dt + l*DII, nullptr,
            delta, DII, RTOT, DII, DTRR);
        // scan -> y (includes +u*D and *silu(z))
        scan_kernel<<<dim3(DII/256, BB), 256>>>(
            delta, dbc, xc, xz, A_log + (size_t)l*DII*DSS, Dmat + l*DII, y);
        // h += y @ w_outproj^T
        gemm_kernel<0,false,true><<<dim3(DMM/64, GM), 256>>>(
            y, DII, w_outproj + (size_t)l*DMM*DII, nullptr, h,
            h, DMM, RTOT, DMM, DII);
        // ln2
        ln_kernel<<<RTOT, 256>>>(h, ln2_w + l*DMM, ln2_b + l*DMM, xln);
        // ff1: f = gelu(xln @ ff_w1^T + b1)   (reuse y as f buffer, 2048x1536)
        gemm_kernel<1,true,false><<<dim3((2*DMM)/64, GM), 256>>>(
            xln, DMM, ff_w1 + (size_t)l*2*DMM*DMM, ff_b1 + l*2*DMM, nullptr,
            y, 2*DMM, RTOT, 2*DMM, DMM);
        // h += f @ ff_w2^T + b2
        gemm_kernel<0,true,true><<<dim3(DMM/64, GM), 256>>>(
            y, 2*DMM, ff_w2 + (size_t)l*DMM*2*DMM, ff_b2 + l*DMM, h,
            h, DMM, RTOT, DMM, 2*DMM);
    }

    headrow_kernel<<<RTOT, 256>>>(h, lnf_w, lnf_b, w_head, rowdot);
    final_kernel<<<BB, 256>>>(rowdot, b_head, out);
}

// round 2
// speedup vs baseline: 1.0327x; 1.0327x over previous
#include <cuda_runtime.h>
#include <math.h>

#define BB   4
#define SS   512
#define DMM  768
#define LLN  2
#define DII  1536
#define DSS  16
#define KKC  4
#define DTRR 48
#define RTOT (BB*SS)         // 2048
#define DBCW (DTRR + 2*DSS)  // 80
#define XSPLIT 16            // split-K slices for xproj

// -------------------- scratch (device globals; no allocs) --------------------
__device__ float g_h    [RTOT*DMM];
__device__ float g_xln  [RTOT*DMM];
__device__ float g_xz   [RTOT*2*DII];
__device__ float g_xc   [RTOT*DII];
__device__ float g_dbc  [RTOT*DBCW];
__device__ float g_delta[RTOT*DII];
__device__ float g_y    [RTOT*DII];
__device__ float g_part [XSPLIT*RTOT*DBCW];
__device__ float g_rowdot[RTOT];

// -------------------- embed: h = x*w_in + b_in + pe --------------------
__global__ void embed_kernel(const float* __restrict__ x, const float* __restrict__ w_in,
                             const float* __restrict__ b_in, const float* __restrict__ pe,
                             float* __restrict__ h) {
    int idx = blockIdx.x * blockDim.x + threadIdx.x;
    if (idx >= RTOT*DMM) return;
    int r = idx / DMM;
    int d = idx - r*DMM;
    int s = r & (SS-1);
    h[idx] = x[r]*w_in[d] + b_in[d] + pe[s*DMM + d];
}

// -------------------- layernorm (row = 768) --------------------
__global__ __launch_bounds__(256) void ln_kernel(const float* __restrict__ x,
                                                 const float* __restrict__ w,
                                                 const float* __restrict__ b,
                                                 float* __restrict__ y) {
    int row = blockIdx.x;
    const float* xr = x + (size_t)row*DMM;
    float v[3];
    float s = 0.f, sq = 0.f;
#pragma unroll
    for (int i = 0; i < 3; i++) {
        v[i] = xr[threadIdx.x + 256*i];
        s  += v[i];
        sq += v[i]*v[i];
    }
    __shared__ float sms[8], smq[8];
    __shared__ float mu_s, rs_s;
#pragma unroll
    for (int o = 16; o > 0; o >>= 1) {
        s  += __shfl_xor_sync(0xffffffffu, s,  o);
        sq += __shfl_xor_sync(0xffffffffu, sq, o);
    }
    int lane = threadIdx.x & 31, wid = threadIdx.x >> 5;
    if (lane == 0) { sms[wid] = s; smq[wid] = sq; }
    __syncthreads();
    if (threadIdx.x == 0) {
        float S = 0.f, Q = 0.f;
        for (int i = 0; i < 8; i++) { S += sms[i]; Q += smq[i]; }
        float mu = S * (1.0f/DMM);
        float var = Q * (1.0f/DMM) - mu*mu;
        mu_s = mu;
        rs_s = rsqrtf(var + 1e-5f);
    }
    __syncthreads();
    float mu = mu_s, rs = rs_s;
    float* yr = y + (size_t)row*DMM;
#pragma unroll
    for (int i = 0; i < 3; i++) {
        int d = threadIdx.x + 256*i;
        yr[d] = (v[i]-mu)*rs*w[d] + b[d];
    }
}

// -------------------- double-buffered SGEMM --------------------
// C[M,N] = act(A[M,K] @ B[N,K]^T + bias) (+res)
// BM=128 fixed, BK=8, 256 threads, micro-tile 8 x (BN/16).
// SPLIT: write raw partials to part + blockIdx.z*M*ldc (K-slice per z).
// ACT: 0 none, 1 gelu(exact), 2 softplus
template<int BN, int ACT, bool HAS_BIAS, bool HAS_RES, bool SPLIT>
__global__ __launch_bounds__(256) void gemm2(
    const float* __restrict__ A, int lda,
    const float* __restrict__ Bw, int ldb,     // (N, K) row-major
    const float* __restrict__ bias,
    const float* res,
    float* C, int ldc,
    int M, int N, int Kd, int kSlice,
    float* part)
{
    const int BM = 128, BK = 8, TM = 8;
    const int TN = BN / 16;
    __shared__ float As[2][BK][BM+4];
    __shared__ float Bs[2][BK][BN+4];

    int tid = threadIdx.x;
    int tx = tid & 15, ty = tid >> 4;
    int m0 = blockIdx.y * BM;
    int n0 = blockIdx.x * BN;
    int kBegin = SPLIT ? blockIdx.z * kSlice : 0;
    int kCount = SPLIT ? kSlice : Kd;

    float acc[TM][TN];
#pragma unroll
    for (int i = 0; i < TM; i++)
#pragma unroll
        for (int j = 0; j < TN; j++) acc[i][j] = 0.f;

    // tile loader into buffer `buf`
    auto loadTiles = [&](int k0, int buf) {
        {   // A: 128x8 = 256 float4, one per thread
            int m = tid >> 1;
            int kv = (tid & 1) * 4;
            float4 v = *reinterpret_cast<const float4*>(A + (size_t)(m0+m)*lda + k0 + kv);
            As[buf][kv+0][m] = v.x; As[buf][kv+1][m] = v.y;
            As[buf][kv+2][m] = v.z; As[buf][kv+3][m] = v.w;
        }
#pragma unroll
        for (int f = tid; f < BN*BK/4; f += 256) {  // B: BNx8
            int n = f >> 1;
            int kv = (f & 1) * 4;
            float4 v = make_float4(0.f,0.f,0.f,0.f);
            if (n0 + n < N)
                v = *reinterpret_cast<const float4*>(Bw + (size_t)(n0+n)*ldb + k0 + kv);
            Bs[buf][kv+0][n] = v.x; Bs[buf][kv+1][n] = v.y;
            Bs[buf][kv+2][n] = v.z; Bs[buf][kv+3][n] = v.w;
        }
    };

    loadTiles(kBegin, 0);
    __syncthreads();

    int nIter = kCount / BK;
    for (int it = 0; it < nIter; it++) {
        int buf = it & 1;
        if (it + 1 < nIter) loadTiles(kBegin + (it+1)*BK, buf ^ 1);
#pragma unroll
        for (int k = 0; k < BK; k++) {
            float am[TM], bn[TN];
            {
                float4 a0 = *reinterpret_cast<const float4*>(&As[buf][k][ty*TM]);
                float4 a1 = *reinterpret_cast<const float4*>(&As[buf][k][ty*TM+4]);
                am[0]=a0.x; am[1]=a0.y; am[2]=a0.z; am[3]=a0.w;
                am[4]=a1.x; am[5]=a1.y; am[6]=a1.z; am[7]=a1.w;
            }
            if (TN == 8) {
                float4 b0 = *reinterpret_cast<const float4*>(&Bs[buf][k][tx*TN]);
                float4 b1 = *reinterpret_cast<const float4*>(&Bs[buf][k][tx*TN+4]);
                bn[0]=b0.x; bn[1]=b0.y; bn[2]=b0.z; bn[3]=b0.w;
                bn[4]=b1.x; bn[5]=b1.y; bn[6]=b1.z; bn[7]=b1.w;
            } else {
                float4 b0 = *reinterpret_cast<const float4*>(&Bs[buf][k][tx*TN]);
                bn[0]=b0.x; bn[1]=b0.y; bn[2]=b0.z; bn[3]=b0.w;
            }
#pragma unroll
            for (int i = 0; i < TM; i++)
#pragma unroll
                for (int j = 0; j < TN; j++)
                    acc[i][j] = fmaf(am[i], bn[j], acc[i][j]);
        }
        __syncthreads();
    }

    float* outp = SPLIT ? (part + (size_t)blockIdx.z * M * ldc) : C;
#pragma unroll
    for (int i = 0; i < TM; i++) {
        int m = m0 + ty*TM + i;
#pragma unroll
        for (int j = 0; j < TN; j++) {
            int n = n0 + tx*TN + j;
            if (n < N) {
                float v = acc[i][j];
                if (!SPLIT) {
                    if (HAS_BIAS) v += bias[n];
                    if (ACT == 1) v = 0.5f * v * (1.0f + erff(v * 0.70710678118654752f));
                    else if (ACT == 2) v = (v > 20.f) ? v : log1pf(__expf(v));
                    if (HAS_RES) v += res[(size_t)m*ldc + n];
                }
                outp[(size_t)m*ldc + n] = v;
            }
        }
    }
}

// reduce split-K partials: out[i] = sum_s part[s*MN + i]
__global__ void reduce_splitk(const float* __restrict__ part, float* __restrict__ out, int MN) {
    int i = blockIdx.x*256 + threadIdx.x;
    if (i >= MN) return;
    float s = 0.f;
#pragma unroll
    for (int k = 0; k < XSPLIT; k++) s += part[(size_t)k*MN + i];
    out[i] = s;
}

// -------------------- causal depthwise conv (K=4) + silu --------------------
__global__ void conv_silu_kernel(const float* __restrict__ xz,
                                 const float* __restrict__ cw,
                                 const float* __restrict__ cb,
                                 float* __restrict__ xc) {
    int idx = blockIdx.x * blockDim.x + threadIdx.x;
    if (idx >= RTOT*DII) return;
    int d = idx % DII;
    int r = idx / DII;
    int s = r & (SS-1);
    float acc = cb[d];
#pragma unroll
    for (int k = 0; k < KKC; k++) {
        int sk = s - (KKC-1) + k;
        if (sk >= 0)
            acc = fmaf(xz[(size_t)(r + sk - s)*(2*DII) + d], cw[d*KKC + k], acc);
    }
    float sg = 1.f / (1.f + __expf(-acc));
    xc[idx] = acc * sg;
}

// -------------------- selective scan --------------------
// one thread per (b,d); 128 threads/CTA -> 48 CTAs; B/C staged in smem
__global__ __launch_bounds__(128) void scan_kernel(
    const float* __restrict__ delta, const float* __restrict__ dbc,
    const float* __restrict__ xc,    const float* __restrict__ xz,
    const float* __restrict__ A_log, const float* __restrict__ Dw,
    float* __restrict__ y)
{
    int b = blockIdx.y;
    int d = blockIdx.x*128 + threadIdx.x;

    float Av[DSS];
#pragma unroll
    for (int i = 0; i < DSS; i++) Av[i] = -__expf(A_log[d*DSS + i]);
    float a0 = Av[0];
    bool fast = true;
#pragma unroll
    for (int i = 0; i < DSS; i++)
        if (fabsf(Av[i] - (float)(i+1)*a0) > 1e-4f*fabsf(Av[i]) + 1e-6f) fast = false;

    float Dd = Dw[d];
    float h[DSS];
#pragma unroll
    for (int i = 0; i < DSS; i++) h[i] = 0.f;

    __shared__ float sBC[32][33];

    for (int s0 = 0; s0 < SS; s0 += 32) {
        __syncthreads();
#pragma unroll
        for (int q = 0; q < 8; q++) {
            int f = threadIdx.x + q*128;
            int j = f >> 5, c = f & 31;
            sBC[j][c] = dbc[(size_t)(b*SS + s0 + j)*DBCW + DTRR + c];
        }
        __syncthreads();
        for (int j = 0; j < 32; j++) {
            size_t r = (size_t)(b*SS + s0 + j);
            float dl = delta[r*DII + d];
            float u  = xc[r*DII + d];
            float du = dl*u;
            float yacc = 0.f;
            if (fast) {
                float t = __expf(dl*a0);
                float p = 1.f;
#pragma unroll
                for (int i = 0; i < DSS; i++) {
                    p *= t;
                    h[i] = fmaf(h[i], p, du*sBC[j][i]);
                    yacc = fmaf(h[i], sBC[j][16+i], yacc);
                }
            } else {
#pragma unroll
                for (int i = 0; i < DSS; i++) {
                    float e = __expf(dl*Av[i]);
                    h[i] = fmaf(h[i], e, du*sBC[j][i]);
                    yacc = fmaf(h[i], sBC[j][16+i], yacc);
                }
            }
            float ys = yacc + u*Dd;
            float z  = xz[r*(2*DII) + DII + d];
            float sg = 1.f / (1.f + __expf(-z));
            y[r*DII + d] = ys * (z*sg);
        }
    }
}

// -------------------- final LN + dot(w_head) per row --------------------
__global__ __launch_bounds__(256) void headrow_kernel(const float* __restrict__ x,
                                                      const float* __restrict__ w,
                                                      const float* __restrict__ b,
                                                      const float* __restrict__ wh,
                                                      float* __restrict__ rowdot) {
    int row = blockIdx.x;
    const float* xr = x + (size_t)row*DMM;
    float v[3];
    float s = 0.f, sq = 0.f;
#pragma unroll
    for (int i = 0; i < 3; i++) {
        v[i] = xr[threadIdx.x + 256*i];
        s += v[i]; sq += v[i]*v[i];
    }
    __shared__ float sms[8], smq[8];
    __shared__ float mu_s, rs_s;
#pragma unroll
    for (int o = 16; o > 0; o >>= 1) {
        s  += __shfl_xor_sync(0xffffffffu, s,  o);
        sq += __shfl_xor_sync(0xffffffffu, sq, o);
    }
    int lane = threadIdx.x & 31, wid = threadIdx.x >> 5;
    if (lane == 0) { sms[wid] = s; smq[wid] = sq; }
    __syncthreads();
    if (threadIdx.x == 0) {
        float S = 0.f, Q = 0.f;
        for (int i = 0; i < 8; i++) { S += sms[i]; Q += smq[i]; }
        float mu = S * (1.0f/DMM);
        float var = Q * (1.0f/DMM) - mu*mu;
        mu_s = mu; rs_s = rsqrtf(var + 1e-5f);
    }
    __syncthreads();
    float mu = mu_s, rs = rs_s;
    float p = 0.f;
#pragma unroll
    for (int i = 0; i < 3; i++) {
        int d = threadIdx.x + 256*i;
        p = fmaf((v[i]-mu)*rs*w[d] + b[d], wh[d], p);
    }
#pragma unroll
    for (int o = 16; o > 0; o >>= 1) p += __shfl_xor_sync(0xffffffffu, p, o);
    __syncthreads();
    if (lane == 0) sms[wid] = p;
    __syncthreads();
    if (threadIdx.x == 0) {
        float S = 0.f;
        for (int i = 0; i < 8; i++) S += sms[i];
        rowdot[row] = S;
    }
}

__global__ __launch_bounds__(256) void final_kernel(const float* __restrict__ rowdot,
                                                    const float* __restrict__ b_head,
                                                    float* __restrict__ out) {
    int b = blockIdx.x;
    float s = 0.f;
    for (int j = threadIdx.x; j < SS; j += 256) s += rowdot[b*SS + j];
    __shared__ float sms[8];
#pragma unroll
    for (int o = 16; o > 0; o >>= 1) s += __shfl_xor_sync(0xffffffffu, s, o);
    int lane = threadIdx.x & 31, wid = threadIdx.x >> 5;
    if (lane == 0) sms[wid] = s;
    __syncthreads();
    if (threadIdx.x == 0) {
        float S = 0.f;
        for (int i = 0; i < 8; i++) S += sms[i];
        out[b] = b_head[0] + S * (1.0f/SS);
    }
}

// -------------------- launch --------------------
extern "C" void kernel_launch(void* const* d_in, const int* in_sizes, int n_in,
                              void* d_out, int out_size) {
    const float* x        = (const float*)d_in[0];
    const float* w_in     = (const float*)d_in[1];
    const float* b_in     = (const float*)d_in[2];
    const float* pe       = (const float*)d_in[3];
    const float* ln1_w    = (const float*)d_in[4];
    const float* ln1_b    = (const float*)d_in[5];
    const float* w_inproj = (const float*)d_in[6];
    const float* conv_w   = (const float*)d_in[7];
    const float* conv_b   = (const float*)d_in[8];
    const float* w_xproj  = (const float*)d_in[9];
    const float* w_dt     = (const float*)d_in[10];
    const float* b_dt     = (const float*)d_in[11];
    const float* A_log    = (const float*)d_in[12];
    const float* Dmat     = (const float*)d_in[13];
    const float* w_outproj= (const float*)d_in[14];
    const float* ln2_w    = (const float*)d_in[15];
    const float* ln2_b    = (const float*)d_in[16];
    const float* ff_w1    = (const float*)d_in[17];
    const float* ff_b1    = (const float*)d_in[18];
    const float* ff_w2    = (const float*)d_in[19];
    const float* ff_b2    = (const float*)d_in[20];
    const float* lnf_w    = (const float*)d_in[21];
    const float* lnf_b    = (const float*)d_in[22];
    const float* w_head   = (const float*)d_in[23];
    const float* b_head   = (const float*)d_in[24];
    float* out = (float*)d_out;

    float *h, *xln, *xz, *xc, *dbc, *delta, *y, *part, *rowdot;
    cudaGetSymbolAddress((void**)&h,     g_h);
    cudaGetSymbolAddress((void**)&xln,   g_xln);
    cudaGetSymbolAddress((void**)&xz,    g_xz);
    cudaGetSymbolAddress((void**)&xc,    g_xc);
    cudaGetSymbolAddress((void**)&dbc,   g_dbc);
    cudaGetSymbolAddress((void**)&delta, g_delta);
    cudaGetSymbolAddress((void**)&y,     g_y);
    cudaGetSymbolAddress((void**)&part,  g_part);
    cudaGetSymbolAddress((void**)&rowdot,g_rowdot);

    const int GM = RTOT/128;  // 16 row-blocks

    embed_kernel<<<(RTOT*DMM + 255)/256, 256>>>(x, w_in, b_in, pe, h);

    for (int l = 0; l < LLN; l++) {
        // ln1
        ln_kernel<<<RTOT, 256>>>(h, ln1_w + l*DMM, ln1_b + l*DMM, xln);
        // inproj: xz[2048,3072] = xln @ w_inproj^T
        gemm2<128,0,false,false,false><<<dim3((2*DII)/128, GM), 256>>>(
            xln, DMM, w_inproj + (size_t)l*2*DII*DMM, DMM, nullptr, nullptr,
            xz, 2*DII, RTOT, 2*DII, DMM, DMM, nullptr);
        // conv + silu
        conv_silu_kernel<<<(RTOT*DII + 255)/256, 256>>>(
            xz, conv_w + (size_t)l*DII*KKC, conv_b + l*DII, xc);
        // xproj (split-K): dbc[2048,80] = xc @ w_xproj^T
        gemm2<128,0,false,false,true><<<dim3(1, GM, XSPLIT), 256>>>(
            xc, DII, w_xproj + (size_t)l*DBCW*DII, DII, nullptr, nullptr,
            nullptr, DBCW, RTOT, DBCW, DII, DII/XSPLIT, part);
        reduce_splitk<<<(RTOT*DBCW + 255)/256, 256>>>(part, dbc, RTOT*DBCW);
        // delta = softplus(dbc[:, :48] @ w_dt^T + b_dt)
        gemm2<128,2,true,false,false><<<dim3(DII/128, GM), 256>>>(
            dbc, DBCW, w_dt + (size_t)l*DII*DTRR, DTRR, b_dt + l*DII, nullptr,
            delta, DII, RTOT, DII, DTRR, DTRR, nullptr);
        // scan -> y
        scan_kernel<<<dim3(DII/128, BB), 128>>>(
            delta, dbc, xc, xz, A_log + (size_t)l*DII*DSS, Dmat + l*DII, y);
        // h += y @ w_outproj^T  (BN=64 -> 192 CTAs)
        gemm2<64,0,false,true,false><<<dim3(DMM/64, GM), 256>>>(
            y, DII, w_outproj + (size_t)l*DMM*DII, DII, nullptr, h,
            h, DMM, RTOT, DMM, DII, DII, nullptr);
        // ln2
        ln_kernel<<<RTOT, 256>>>(h, ln2_w + l*DMM, ln2_b + l*DMM, xln);
        // ff1: f = gelu(xln @ ff_w1^T + b1)  (f in g_y, 2048x1536)
        gemm2<128,1,true,false,false><<<dim3((2*DMM)/128, GM), 256>>>(
            xln, DMM, ff_w1 + (size_t)l*2*DMM*DMM, DMM, ff_b1 + l*2*DMM, nullptr,
            y, 2*DMM, RTOT, 2*DMM, DMM, DMM, nullptr);
        // h += f @ ff_w2^T + b2  (BN=64 -> 192 CTAs)
        gemm2<64,0,true,true,false><<<dim3(DMM/64, GM), 256>>>(
            y, 2*DMM, ff_w2 + (size_t)l*DMM*2*DMM, 2*DMM, ff_b2 + l*DMM, h,
            h, DMM, RTOT, DMM, 2*DMM, 2*DMM, nullptr);
    }

    headrow_kernel<<<RTOT, 256>>>(h, lnf_w, lnf_b, w_head, rowdot);
    final_kernel<<<BB, 256>>>(rowdot, b_head, out);
}

// round 3
// speedup vs baseline: 1.7217x; 1.6671x over previous
#include <cuda_runtime.h>
#include <math.h>
#include <stdint.h>

#define BB   4
#define SS   512
#define DMM  768
#define LLN  2
#define DII  1536
#define DSS  16
#define KKC  4
#define DTRR 48
#define RTOT (BB*SS)         // 2048
#define DBCW (DTRR + 2*DSS)  // 80
#define XSPLIT 16            // split-K slices for xproj

// -------------------- scratch (device globals; no allocs) --------------------
__device__ float g_h    [RTOT*DMM];
__device__ float g_xln  [RTOT*DMM];
__device__ float g_xz   [RTOT*2*DII];
__device__ float g_xc   [RTOT*DII];
__device__ float g_dbc  [RTOT*DBCW];
__device__ float g_delta[RTOT*DII];
__device__ float g_y    [RTOT*DII];
__device__ float g_part [XSPLIT*RTOT*DBCW];
__device__ float g_rowdot[RTOT];

// -------------------- helpers --------------------
__device__ __forceinline__ uint32_t f2tf32(float x) {
    uint32_t r;
    asm("cvt.rna.tf32.f32 %0, %1;" : "=r"(r) : "f"(x));
    return r;
}
__device__ __forceinline__ void mma_tf32(float* c, const uint32_t* a, const uint32_t* b) {
    asm volatile(
        "mma.sync.aligned.m16n8k8.row.col.f32.tf32.tf32.f32 "
        "{%0,%1,%2,%3}, {%4,%5,%6,%7}, {%8,%9}, {%0,%1,%2,%3};"
        : "+f"(c[0]), "+f"(c[1]), "+f"(c[2]), "+f"(c[3])
        : "r"(a[0]), "r"(a[1]), "r"(a[2]), "r"(a[3]), "r"(b[0]), "r"(b[1]));
}
__device__ __forceinline__ float gelu_exact(float v) {
    return 0.5f * v * (1.0f + erff(v * 0.70710678118654752f));
}

// -------------------- embed --------------------
__global__ void embed_kernel(const float* __restrict__ x, const float* __restrict__ w_in,
                             const float* __restrict__ b_in, const float* __restrict__ pe,
                             float* __restrict__ h) {
    int idx = blockIdx.x * blockDim.x + threadIdx.x;
    if (idx >= RTOT*DMM) return;
    int r = idx / DMM;
    int d = idx - r*DMM;
    int s = r & (SS-1);
    h[idx] = x[r]*w_in[d] + b_in[d] + pe[s*DMM + d];
}

// -------------------- layernorm --------------------
__global__ __launch_bounds__(256) void ln_kernel(const float* __restrict__ x,
                                                 const float* __restrict__ w,
                                                 const float* __restrict__ b,
                                                 float* __restrict__ y) {
    int row = blockIdx.x;
    const float* xr = x + (size_t)row*DMM;
    float v[3];
    float s = 0.f, sq = 0.f;
#pragma unroll
    for (int i = 0; i < 3; i++) {
        v[i] = xr[threadIdx.x + 256*i];
        s  += v[i];
        sq += v[i]*v[i];
    }
    __shared__ float sms[8], smq[8];
    __shared__ float mu_s, rs_s;
#pragma unroll
    for (int o = 16; o > 0; o >>= 1) {
        s  += __shfl_xor_sync(0xffffffffu, s,  o);
        sq += __shfl_xor_sync(0xffffffffu, sq, o);
    }
    int lane = threadIdx.x & 31, wid = threadIdx.x >> 5;
    if (lane == 0) { sms[wid] = s; smq[wid] = sq; }
    __syncthreads();
    if (threadIdx.x == 0) {
        float S = 0.f, Q = 0.f;
        for (int i = 0; i < 8; i++) { S += sms[i]; Q += smq[i]; }
        float mu = S * (1.0f/DMM);
        float var = Q * (1.0f/DMM) - mu*mu;
        mu_s = mu;
        rs_s = rsqrtf(var + 1e-5f);
    }
    __syncthreads();
    float mu = mu_s, rs = rs_s;
    float* yr = y + (size_t)row*DMM;
#pragma unroll
    for (int i = 0; i < 3; i++) {
        int d = threadIdx.x + 256*i;
        yr[d] = (v[i]-mu)*rs*w[d] + b[d];
    }
}

// -------------------- tensor-core tf32 GEMM --------------------
// C[M,N] = act(A[M,K] @ B[N,K]^T + bias) (+res)
// BM=128, BK=16, 256 threads. Both A and B staged [row][k] stride 20 (bank-clean).
// BN=128: warps 2(m)x4(n), warp tile 64x32. BN=64: warps 4x2, warp tile 32x32.
template<int BN, int ACT, bool HAS_BIAS, bool HAS_RES>
__global__ __launch_bounds__(256, 2) void gemm_tc(
    const float* __restrict__ A, int lda,
    const float* __restrict__ Bw, int ldb,     // (N, K) row-major
    const float* __restrict__ bias,
    const float* res,
    float* C, int ldc,
    int M, int N, int Kd)
{
    const int BM = 128, SK = 20;
    const int WC = (BN == 128) ? 4 : 2;          // warps along n
    const int WARP_M = (BN == 128) ? 64 : 32;
    const int WARP_N = 32;
    const int MT = WARP_M / 16;                  // m16 tiles per warp
    const int NT = WARP_N / 8;                   // n8 tiles per warp

    __shared__ float As[2][BM][SK];
    __shared__ float Bs[2][BN][SK];

    int tid  = threadIdx.x;
    int wid  = tid >> 5;
    int lane = tid & 31;
    int g    = lane >> 2;        // groupID
    int tg   = lane & 3;         // threadID_in_group
    int wm = (wid / WC) * WARP_M;
    int wn = (wid % WC) * WARP_N;
    int m0 = blockIdx.y * BM;
    int n0 = blockIdx.x * BN;

    float acc[MT][NT][4];
#pragma unroll
    for (int i = 0; i < MT; i++)
#pragma unroll
        for (int j = 0; j < NT; j++)
#pragma unroll
            for (int q = 0; q < 4; q++) acc[i][j][q] = 0.f;

    auto stage = [&](int k0, int buf) {
        // A: 128x16 floats = 512 float4, 2 per thread
#pragma unroll
        for (int q = 0; q < 2; q++) {
            int f = tid + q*256;
            int m = f >> 2, kv = (f & 3) * 4;
            float4 v = *reinterpret_cast<const float4*>(A + (size_t)(m0+m)*lda + k0 + kv);
            float4 w;
            w.x = __uint_as_float(f2tf32(v.x));
            w.y = __uint_as_float(f2tf32(v.y));
            w.z = __uint_as_float(f2tf32(v.z));
            w.w = __uint_as_float(f2tf32(v.w));
            *reinterpret_cast<float4*>(&As[buf][m][kv]) = w;
        }
        // B: BNx16 floats
#pragma unroll
        for (int q = 0; q < BN/64; q++) {
            int f = tid + q*256;
            int n = f >> 2, kv = (f & 3) * 4;
            float4 v = make_float4(0.f, 0.f, 0.f, 0.f);
            if (n0 + n < N)
                v = *reinterpret_cast<const float4*>(Bw + (size_t)(n0+n)*ldb + k0 + kv);
            float4 w;
            w.x = __uint_as_float(f2tf32(v.x));
            w.y = __uint_as_float(f2tf32(v.y));
            w.z = __uint_as_float(f2tf32(v.z));
            w.w = __uint_as_float(f2tf32(v.w));
            *reinterpret_cast<float4*>(&Bs[buf][n][kv]) = w;
        }
    };

    stage(0, 0);
    __syncthreads();

    int nIter = Kd / 16;
    for (int it = 0; it < nIter; it++) {
        int buf = it & 1;
        if (it + 1 < nIter) stage((it+1)*16, buf ^ 1);
#pragma unroll
        for (int kk = 0; kk < 2; kk++) {
            int kb = kk*8;
            uint32_t bf[NT][2];
#pragma unroll
            for (int tn = 0; tn < NT; tn++) {
                int n = wn + tn*8 + g;
                bf[tn][0] = __float_as_uint(Bs[buf][n][kb + tg]);
                bf[tn][1] = __float_as_uint(Bs[buf][n][kb + tg + 4]);
            }
#pragma unroll
            for (int tm = 0; tm < MT; tm++) {
                int r = wm + tm*16 + g;
                uint32_t af[4];
                af[0] = __float_as_uint(As[buf][r    ][kb + tg    ]);
                af[1] = __float_as_uint(As[buf][r + 8][kb + tg    ]);
                af[2] = __float_as_uint(As[buf][r    ][kb + tg + 4]);
                af[3] = __float_as_uint(As[buf][r + 8][kb + tg + 4]);
#pragma unroll
                for (int tn = 0; tn < NT; tn++)
                    mma_tf32(acc[tm][tn], af, bf[tn]);
            }
        }
        __syncthreads();
    }

    // epilogue
#pragma unroll
    for (int tm = 0; tm < MT; tm++) {
        int mrow = m0 + wm + tm*16 + g;
#pragma unroll
        for (int tn = 0; tn < NT; tn++) {
            int ncol = n0 + wn + tn*8 + 2*tg;
            if (ncol < N) {
                float b0v = 0.f, b1v = 0.f;
                if (HAS_BIAS) { b0v = bias[ncol]; b1v = bias[ncol+1]; }
                float v0 = acc[tm][tn][0] + b0v;
                float v1 = acc[tm][tn][1] + b1v;
                float v2 = acc[tm][tn][2] + b0v;
                float v3 = acc[tm][tn][3] + b1v;
                if (ACT == 1) {
                    v0 = gelu_exact(v0); v1 = gelu_exact(v1);
                    v2 = gelu_exact(v2); v3 = gelu_exact(v3);
                }
                size_t o0 = (size_t)mrow*ldc + ncol;
                size_t o1 = (size_t)(mrow+8)*ldc + ncol;
                if (HAS_RES) {
                    float2 r0 = *reinterpret_cast<const float2*>(res + o0);
                    float2 r1 = *reinterpret_cast<const float2*>(res + o1);
                    v0 += r0.x; v1 += r0.y; v2 += r1.x; v3 += r1.y;
                }
                *reinterpret_cast<float2*>(C + o0) = make_float2(v0, v1);
                *reinterpret_cast<float2*>(C + o1) = make_float2(v2, v3);
            }
        }
    }
}

// -------------------- fp32 SIMT GEMM (small/precision-critical) --------------------
template<int BN, int ACT, bool HAS_BIAS, bool HAS_RES, bool SPLIT>
__global__ __launch_bounds__(256) void gemm2(
    const float* __restrict__ A, int lda,
    const float* __restrict__ Bw, int ldb,
    const float* __restrict__ bias,
    const float* res,
    float* C, int ldc,
    int M, int N, int Kd, int kSlice,
    float* part)
{
    const int BM = 128, BK = 8, TM = 8;
    const int TN = BN / 16;
    __shared__ float As[2][BK][BM+4];
    __shared__ float Bs[2][BK][BN+4];

    int tid = threadIdx.x;
    int tx = tid & 15, ty = tid >> 4;
    int m0 = blockIdx.y * BM;
    int n0 = blockIdx.x * BN;
    int kBegin = SPLIT ? blockIdx.z * kSlice : 0;
    int kCount = SPLIT ? kSlice : Kd;

    float acc[TM][TN];
#pragma unroll
    for (int i = 0; i < TM; i++)
#pragma unroll
        for (int j = 0; j < TN; j++) acc[i][j] = 0.f;

    auto loadTiles = [&](int k0, int buf) {
        {
            int m = tid >> 1;
            int kv = (tid & 1) * 4;
            float4 v = *reinterpret_cast<const float4*>(A + (size_t)(m0+m)*lda + k0 + kv);
            As[buf][kv+0][m] = v.x; As[buf][kv+1][m] = v.y;
            As[buf][kv+2][m] = v.z; As[buf][kv+3][m] = v.w;
        }
#pragma unroll
        for (int f = tid; f < BN*BK/4; f += 256) {
            int n = f >> 1;
            int kv = (f & 1) * 4;
            float4 v = make_float4(0.f,0.f,0.f,0.f);
            if (n0 + n < N)
                v = *reinterpret_cast<const float4*>(Bw + (size_t)(n0+n)*ldb + k0 + kv);
            Bs[buf][kv+0][n] = v.x; Bs[buf][kv+1][n] = v.y;
            Bs[buf][kv+2][n] = v.z; Bs[buf][kv+3][n] = v.w;
        }
    };

    loadTiles(kBegin, 0);
    __syncthreads();

    int nIter = kCount / BK;
    for (int it = 0; it < nIter; it++) {
        int buf = it & 1;
        if (it + 1 < nIter) loadTiles(kBegin + (it+1)*BK, buf ^ 1);
#pragma unroll
        for (int k = 0; k < BK; k++) {
            float am[TM], bn[TN];
            {
                float4 a0 = *reinterpret_cast<const float4*>(&As[buf][k][ty*TM]);
                float4 a1 = *reinterpret_cast<const float4*>(&As[buf][k][ty*TM+4]);
                am[0]=a0.x; am[1]=a0.y; am[2]=a0.z; am[3]=a0.w;
                am[4]=a1.x; am[5]=a1.y; am[6]=a1.z; am[7]=a1.w;
            }
            if (TN == 8) {
                float4 b0 = *reinterpret_cast<const float4*>(&Bs[buf][k][tx*TN]);
                float4 b1 = *reinterpret_cast<const float4*>(&Bs[buf][k][tx*TN+4]);
                bn[0]=b0.x; bn[1]=b0.y; bn[2]=b0.z; bn[3]=b0.w;
                bn[4]=b1.x; bn[5]=b1.y; bn[6]=b1.z; bn[7]=b1.w;
            } else {
                float4 b0 = *reinterpret_cast<const float4*>(&Bs[buf][k][tx*TN]);
                bn[0]=b0.x; bn[1]=b0.y; bn[2]=b0.z; bn[3]=b0.w;
            }
#pragma unroll
            for (int i = 0; i < TM; i++)
#pragma unroll
                for (int j = 0; j < TN; j++)
                    acc[i][j] = fmaf(am[i], bn[j], acc[i][j]);
        }
        __syncthreads();
    }

    float* outp = SPLIT ? (part + (size_t)blockIdx.z * M * ldc) : C;
#pragma unroll
    for (int i = 0; i < TM; i++) {
        int m = m0 + ty*TM + i;
#pragma unroll
        for (int j = 0; j < TN; j++) {
            int n = n0 + tx*TN + j;
            if (n < N) {
                float v = acc[i][j];
                if (!SPLIT) {
                    if (HAS_BIAS) v += bias[n];
                    if (ACT == 1) v = gelu_exact(v);
                    else if (ACT == 2) v = (v > 20.f) ? v : log1pf(__expf(v));
                    if (HAS_RES) v += res[(size_t)m*ldc + n];
                }
                outp[(size_t)m*ldc + n] = v;
            }
        }
    }
}

// reduce split-K partials
__global__ void reduce_splitk(const float* __restrict__ part, float* __restrict__ out, int MN) {
    int i = blockIdx.x*256 + threadIdx.x;
    if (i >= MN) return;
    float s = 0.f;
#pragma unroll
    for (int k = 0; k < XSPLIT; k++) s += part[(size_t)k*MN + i];
    out[i] = s;
}

// -------------------- causal depthwise conv (K=4) + silu --------------------
__global__ void conv_silu_kernel(const float* __restrict__ xz,
                                 const float* __restrict__ cw,
                                 const float* __restrict__ cb,
                                 float* __restrict__ xc) {
    int idx = blockIdx.x * blockDim.x + threadIdx.x;
    if (idx >= RTOT*DII) return;
    int d = idx % DII;
    int r = idx / DII;
    int s = r & (SS-1);
    float acc = cb[d];
#pragma unroll
    for (int k = 0; k < KKC; k++) {
        int sk = s - (KKC-1) + k;
        if (sk >= 0)
            acc = fmaf(xz[(size_t)(r + sk - s)*(2*DII) + d], cw[d*KKC + k], acc);
    }
    float sg = 1.f / (1.f + __expf(-acc));
    xc[idx] = acc * sg;
}

// -------------------- selective scan --------------------
__global__ __launch_bounds__(128) void scan_kernel(
    const float* __restrict__ delta, const float* __restrict__ dbc,
    const float* __restrict__ xc,    const float* __restrict__ xz,
    const float* __restrict__ A_log, const float* __restrict__ Dw,
    float* __restrict__ y)
{
    int b = blockIdx.y;
    int d = blockIdx.x*128 + threadIdx.x;

    float Av[DSS];
#pragma unroll
    for (int i = 0; i < DSS; i++) Av[i] = -__expf(A_log[d*DSS + i]);
    float a0 = Av[0];
    bool fast = true;
#pragma unroll
    for (int i = 0; i < DSS; i++)
        if (fabsf(Av[i] - (float)(i+1)*a0) > 1e-4f*fabsf(Av[i]) + 1e-6f) fast = false;

    float Dd = Dw[d];
    float h[DSS];
#pragma unroll
    for (int i = 0; i < DSS; i++) h[i] = 0.f;

    __shared__ float sBC[32][33];

    for (int s0 = 0; s0 < SS; s0 += 32) {
        __syncthreads();
#pragma unroll
        for (int q = 0; q < 8; q++) {
            int f = threadIdx.x + q*128;
            int j = f >> 5, c = f & 31;
            sBC[j][c] = dbc[(size_t)(b*SS + s0 + j)*DBCW + DTRR + c];
        }
        __syncthreads();
        for (int j = 0; j < 32; j++) {
            size_t r = (size_t)(b*SS + s0 + j);
            float dl = delta[r*DII + d];
            float u  = xc[r*DII + d];
            float du = dl*u;
            float yacc = 0.f;
            if (fast) {
                float t = __expf(dl*a0);
                float p = 1.f;
#pragma unroll
                for (int i = 0; i < DSS; i++) {
                    p *= t;
                    h[i] = fmaf(h[i], p, du*sBC[j][i]);
                    yacc = fmaf(h[i], sBC[j][16+i], yacc);
                }
            } else {
#pragma unroll
                for (int i = 0; i < DSS; i++) {
                    float e = __expf(dl*Av[i]);
                    h[i] = fmaf(h[i], e, du*sBC[j][i]);
                    yacc = fmaf(h[i], sBC[j][16+i], yacc);
                }
            }
            float ys = yacc + u*Dd;
            float z  = xz[r*(2*DII) + DII + d];
            float sg = 1.f / (1.f + __expf(-z));
            y[r*DII + d] = ys * (z*sg);
        }
    }
}

// -------------------- final LN + head --------------------
__global__ __launch_bounds__(256) void headrow_kernel(const float* __restrict__ x,
                                                      const float* __restrict__ w,
                                                      const float* __restrict__ b,
                                                      const float* __restrict__ wh,
                                                      float* __restrict__ rowdot) {
    int row = blockIdx.x;
    const float* xr = x + (size_t)row*DMM;
    float v[3];
    float s = 0.f, sq = 0.f;
#pragma unroll
    for (int i = 0; i < 3; i++) {
        v[i] = xr[threadIdx.x + 256*i];
        s += v[i]; sq += v[i]*v[i];
    }
    __shared__ float sms[8], smq[8];
    __shared__ float mu_s, rs_s;
#pragma unroll
    for (int o = 16; o > 0; o >>= 1) {
        s  += __shfl_xor_sync(0xffffffffu, s,  o);
        sq += __shfl_xor_sync(0xffffffffu, sq, o);
    }
    int lane = threadIdx.x & 31, wid = threadIdx.x >> 5;
    if (lane == 0) { sms[wid] = s; smq[wid] = sq; }
    __syncthreads();
    if (threadIdx.x == 0) {
        float S = 0.f, Q = 0.f;
        for (int i = 0; i < 8; i++) { S += sms[i]; Q += smq[i]; }
        float mu = S * (1.0f/DMM);
        float var = Q * (1.0f/DMM) - mu*mu;
        mu_s = mu; rs_s = rsqrtf(var + 1e-5f);
    }
    __syncthreads();
    float mu = mu_s, rs = rs_s;
    float p = 0.f;
#pragma unroll
    for (int i = 0; i < 3; i++) {
        int d = threadIdx.x + 256*i;
        p = fmaf((v[i]-mu)*rs*w[d] + b[d], wh[d], p);
    }
#pragma unroll
    for (int o = 16; o > 0; o >>= 1) p += __shfl_xor_sync(0xffffffffu, p, o);
    __syncthreads();
    if (lane == 0) sms[wid] = p;
    __syncthreads();
    if (threadIdx.x == 0) {
        float S = 0.f;
        for (int i = 0; i < 8; i++) S += sms[i];
        rowdot[row] = S;
    }
}

__global__ __launch_bounds__(256) void final_kernel(const float* __restrict__ rowdot,
                                                    const float* __restrict__ b_head,
                                                    float* __restrict__ out) {
    int b = blockIdx.x;
    float s = 0.f;
    for (int j = threadIdx.x; j < SS; j += 256) s += rowdot[b*SS + j];
    __shared__ float sms[8];
#pragma unroll
    for (int o = 16; o > 0; o >>= 1) s += __shfl_xor_sync(0xffffffffu, s, o);
    int lane = threadIdx.x & 31, wid = threadIdx.x >> 5;
    if (lane == 0) sms[wid] = s;
    __syncthreads();
    if (threadIdx.x == 0) {
        float S = 0.f;
        for (int i = 0; i < 8; i++) S += sms[i];
        out[b] = b_head[0] + S * (1.0f/SS);
    }
}

// -------------------- launch --------------------
extern "C" void kernel_launch(void* const* d_in, const int* in_sizes, int n_in,
                              void* d_out, int out_size) {
    const float* x        = (const float*)d_in[0];
    const float* w_in     = (const float*)d_in[1];
    const float* b_in     = (const float*)d_in[2];
    const float* pe       = (const float*)d_in[3];
    const float* ln1_w    = (const float*)d_in[4];
    const float* ln1_b    = (const float*)d_in[5];
    const float* w_inproj = (const float*)d_in[6];
    const float* conv_w   = (const float*)d_in[7];
    const float* conv_b   = (const float*)d_in[8];
    const float* w_xproj  = (const float*)d_in[9];
    const float* w_dt     = (const float*)d_in[10];
    const float* b_dt     = (const float*)d_in[11];
    const float* A_log    = (const float*)d_in[12];
    const float* Dmat     = (const float*)d_in[13];
    const float* w_outproj= (const float*)d_in[14];
    const float* ln2_w    = (const float*)d_in[15];
    const float* ln2_b    = (const float*)d_in[16];
    const float* ff_w1    = (const float*)d_in[17];
    const float* ff_b1    = (const float*)d_in[18];
    const float* ff_w2    = (const float*)d_in[19];
    const float* ff_b2    = (const float*)d_in[20];
    const float* lnf_w    = (const float*)d_in[21];
    const float* lnf_b    = (const float*)d_in[22];
    const float* w_head   = (const float*)d_in[23];
    const float* b_head   = (const float*)d_in[24];
    float* out = (float*)d_out;

    float *h, *xln, *xz, *xc, *dbc, *delta, *y, *part, *rowdot;
    cudaGetSymbolAddress((void**)&h,     g_h);
    cudaGetSymbolAddress((void**)&xln,   g_xln);
    cudaGetSymbolAddress((void**)&xz,    g_xz);
    cudaGetSymbolAddress((void**)&xc,    g_xc);
    cudaGetSymbolAddress((void**)&dbc,   g_dbc);
    cudaGetSymbolAddress((void**)&delta, g_delta);
    cudaGetSymbolAddress((void**)&y,     g_y);
    cudaGetSymbolAddress((void**)&part,  g_part);
    cudaGetSymbolAddress((void**)&rowdot,g_rowdot);

    const int GM = RTOT/128;  // 16 row-blocks

    embed_kernel<<<(RTOT*DMM + 255)/256, 256>>>(x, w_in, b_in, pe, h);

    for (int l = 0; l < LLN; l++) {
        // ln1
        ln_kernel<<<RTOT, 256>>>(h, ln1_w + l*DMM, ln1_b + l*DMM, xln);
        // inproj: xz[2048,3072] = xln @ w_inproj^T   (TC tf32)
        gemm_tc<128,0,false,false><<<dim3((2*DII)/128, GM), 256>>>(
            xln, DMM, w_inproj + (size_t)l*2*DII*DMM, DMM, nullptr, nullptr,
            xz, 2*DII, RTOT, 2*DII, DMM);
        // conv + silu
        conv_silu_kernel<<<(RTOT*DII + 255)/256, 256>>>(
            xz, conv_w + (size_t)l*DII*KKC, conv_b + l*DII, xc);
        // xproj (split-K, fp32): dbc[2048,80] = xc @ w_xproj^T
        gemm2<128,0,false,false,true><<<dim3(1, GM, XSPLIT), 256>>>(
            xc, DII, w_xproj + (size_t)l*DBCW*DII, DII, nullptr, nullptr,
            nullptr, DBCW, RTOT, DBCW, DII, DII/XSPLIT, part);
        reduce_splitk<<<(RTOT*DBCW + 255)/256, 256>>>(part, dbc, RTOT*DBCW);
        // delta = softplus(dbc[:, :48] @ w_dt^T + b_dt)   (fp32)
        gemm2<128,2,true,false,false><<<dim3(DII/128, GM), 256>>>(
            dbc, DBCW, w_dt + (size_t)l*DII*DTRR, DTRR, b_dt + l*DII, nullptr,
            delta, DII, RTOT, DII, DTRR, DTRR, nullptr);
        // scan -> y
        scan_kernel<<<dim3(DII/128, BB), 128>>>(
            delta, dbc, xc, xz, A_log + (size_t)l*DII*DSS, Dmat + l*DII, y);
        // h += y @ w_outproj^T   (TC tf32, BN=64 -> 192 CTAs)
        gemm_tc<64,0,false,true><<<dim3(DMM/64, GM), 256>>>(
            y, DII, w_outproj + (size_t)l*DMM*DII, DII, nullptr, h,
            h, DMM, RTOT, DMM, DII);
        // ln2
        ln_kernel<<<RTOT, 256>>>(h, ln2_w + l*DMM, ln2_b + l*DMM, xln);
        // ff1: f = gelu(xln @ ff_w1^T + b1)   (TC tf32)
        gemm_tc<128,1,true,false><<<dim3((2*DMM)/128, GM), 256>>>(
            xln, DMM, ff_w1 + (size_t)l*2*DMM*DMM, DMM, ff_b1 + l*2*DMM, nullptr,
            y, 2*DMM, RTOT, 2*DMM, DMM);
        // h += f @ ff_w2^T + b2   (TC tf32, BN=64)
        gemm_tc<64,0,true,true><<<dim3(DMM/64, GM), 256>>>(
            y, 2*DMM, ff_w2 + (size_t)l*DMM*2*DMM, 2*DMM, ff_b2 + l*DMM, h,
            h, DMM, RTOT, DMM, 2*DMM);
    }

    headrow_kernel<<<RTOT, 256>>>(h, lnf_w, lnf_b, w_head, rowdot);
    final_kernel<<<BB, 256>>>(rowdot, b_head, out);
}

// round 4
// speedup vs baseline: 2.4425x; 1.4187x over previous
#include <cuda_runtime.h>
#include <math.h>
#include <stdint.h>

#define BB   4
#define SS   512
#define DMM  768
#define LLN  2
#define DII  1536
#define DSS  16
#define KKC  4
#define DTRR 48
#define RTOT (BB*SS)         // 2048
#define DBCW (DTRR + 2*DSS)  // 80
#define XSPLIT 16            // split-K slices for xproj

// -------------------- scratch (device globals; no allocs) --------------------
__device__ float g_h    [RTOT*DMM];
__device__ float g_xln  [RTOT*DMM];
__device__ float g_xz   [RTOT*2*DII];
__device__ float g_xc   [RTOT*DII];
__device__ float g_dbc  [RTOT*DBCW];
__device__ float g_delta[RTOT*DII];
__device__ float g_y    [RTOT*DII];
__device__ float g_part [XSPLIT*RTOT*DBCW];
__device__ float g_rowdot[RTOT];

// -------------------- helpers --------------------
__device__ __forceinline__ uint32_t f2tf32(float x) {
    uint32_t r;
    asm("cvt.rna.tf32.f32 %0, %1;" : "=r"(r) : "f"(x));
    return r;
}
__device__ __forceinline__ void mma_tf32(float* c, const uint32_t* a, const uint32_t* b) {
    asm volatile(
        "mma.sync.aligned.m16n8k8.row.col.f32.tf32.tf32.f32 "
        "{%0,%1,%2,%3}, {%4,%5,%6,%7}, {%8,%9}, {%0,%1,%2,%3};"
        : "+f"(c[0]), "+f"(c[1]), "+f"(c[2]), "+f"(c[3])
        : "r"(a[0]), "r"(a[1]), "r"(a[2]), "r"(a[3]), "r"(b[0]), "r"(b[1]));
}
__device__ __forceinline__ void cp_async16(uint32_t smem_addr, const float* gptr) {
    asm volatile("cp.async.cg.shared.global [%0], [%1], 16;\n"
                 :: "r"(smem_addr), "l"(gptr));
}
__device__ __forceinline__ void cp_commit() {
    asm volatile("cp.async.commit_group;\n" ::: "memory");
}
template<int N>
__device__ __forceinline__ void cp_wait() {
    asm volatile("cp.async.wait_group %0;\n" :: "n"(N) : "memory");
}
__device__ __forceinline__ float gelu_exact(float v) {
    return 0.5f * v * (1.0f + erff(v * 0.70710678118654752f));
}

// -------------------- embed --------------------
__global__ void embed_kernel(const float* __restrict__ x, const float* __restrict__ w_in,
                             const float* __restrict__ b_in, const float* __restrict__ pe,
                             float* __restrict__ h) {
    int idx = blockIdx.x * blockDim.x + threadIdx.x;
    if (idx >= RTOT*DMM) return;
    int r = idx / DMM;
    int d = idx - r*DMM;
    int s = r & (SS-1);
    h[idx] = x[r]*w_in[d] + b_in[d] + pe[s*DMM + d];
}

// -------------------- layernorm --------------------
__global__ __launch_bounds__(256) void ln_kernel(const float* __restrict__ x,
                                                 const float* __restrict__ w,
                                                 const float* __restrict__ b,
                                                 float* __restrict__ y) {
    int row = blockIdx.x;
    const float* xr = x + (size_t)row*DMM;
    float v[3];
    float s = 0.f, sq = 0.f;
#pragma unroll
    for (int i = 0; i < 3; i++) {
        v[i] = xr[threadIdx.x + 256*i];
        s  += v[i];
        sq += v[i]*v[i];
    }
    __shared__ float sms[8], smq[8];
    __shared__ float mu_s, rs_s;
#pragma unroll
    for (int o = 16; o > 0; o >>= 1) {
        s  += __shfl_xor_sync(0xffffffffu, s,  o);
        sq += __shfl_xor_sync(0xffffffffu, sq, o);
    }
    int lane = threadIdx.x & 31, wid = threadIdx.x >> 5;
    if (lane == 0) { sms[wid] = s; smq[wid] = sq; }
    __syncthreads();
    if (threadIdx.x == 0) {
        float S = 0.f, Q = 0.f;
        for (int i = 0; i < 8; i++) { S += sms[i]; Q += smq[i]; }
        float mu = S * (1.0f/DMM);
        float var = Q * (1.0f/DMM) - mu*mu;
        mu_s = mu;
        rs_s = rsqrtf(var + 1e-5f);
    }
    __syncthreads();
    float mu = mu_s, rs = rs_s;
    float* yr = y + (size_t)row*DMM;
#pragma unroll
    for (int i = 0; i < 3; i++) {
        int d = threadIdx.x + 256*i;
        yr[d] = (v[i]-mu)*rs*w[d] + b[d];
    }
}

// -------------------- tensor-core tf32 GEMM, cp.async 3-stage --------------------
// C[M,N] = act(A[M,K] @ B[N,K]^T + bias) (+res)
// BM=128, BK=16 per stage, 256 threads, dynamic smem.
// Requires: M%128==0, N%BN==0, K%16==0 (all TC call sites satisfy this).
template<int BN, int ACT, bool HAS_BIAS, bool HAS_RES>
__global__ __launch_bounds__(256, 2) void gemm_tc(
    const float* __restrict__ A, int lda,
    const float* __restrict__ Bw, int ldb,     // (N, K) row-major
    const float* __restrict__ bias,
    const float* res,
    float* C, int ldc,
    int M, int N, int Kd)
{
    const int BM = 128, SK = 20, STG = 3;
    const int WC = (BN == 128) ? 4 : 2;          // warps along n
    const int WARP_M = (BN == 128) ? 64 : 32;
    const int WARP_N = 32;
    const int MT = WARP_M / 16;
    const int NT = WARP_N / 8;

    extern __shared__ float sm[];
    float* As = sm;                        // STG * BM * SK
    float* Bs = sm + STG*BM*SK;            // STG * BN * SK

    int tid  = threadIdx.x;
    int wid  = tid >> 5;
    int lane = tid & 31;
    int g    = lane >> 2;
    int tg   = lane & 3;
    int wm = (wid / WC) * WARP_M;
    int wn = (wid % WC) * WARP_N;
    int m0 = blockIdx.y * BM;
    int n0 = blockIdx.x * BN;

    float acc[MT][NT][4];
#pragma unroll
    for (int i = 0; i < MT; i++)
#pragma unroll
        for (int j = 0; j < NT; j++)
#pragma unroll
            for (int q = 0; q < 4; q++) acc[i][j][q] = 0.f;

    auto stageLoad = [&](int k0, int buf) {
        float* Asb = As + buf*BM*SK;
        float* Bsb = Bs + buf*BN*SK;
#pragma unroll
        for (int q = 0; q < 2; q++) {
            int f = tid + q*256;
            int m = f >> 2, kv = (f & 3) * 4;
            cp_async16((uint32_t)__cvta_generic_to_shared(Asb + m*SK + kv),
                       A + (size_t)(m0+m)*lda + k0 + kv);
        }
#pragma unroll
        for (int q = 0; q < BN/64; q++) {
            int f = tid + q*256;
            int n = f >> 2, kv = (f & 3) * 4;
            cp_async16((uint32_t)__cvta_generic_to_shared(Bsb + n*SK + kv),
                       Bw + (size_t)(n0+n)*ldb + k0 + kv);
        }
    };

    int nIter = Kd / 16;
    stageLoad(0, 0);  cp_commit();
    stageLoad(16, 1); cp_commit();

    for (int it = 0; it < nIter; it++) {
        cp_wait<1>();
        __syncthreads();
        int nxt = it + 2;
        if (nxt < nIter) stageLoad(nxt*16, nxt % STG);
        cp_commit();

        int buf = it % STG;
        const float* Asb = As + buf*BM*SK;
        const float* Bsb = Bs + buf*BN*SK;
#pragma unroll
        for (int kk = 0; kk < 2; kk++) {
            int kb = kk*8;
            uint32_t bf[NT][2];
#pragma unroll
            for (int tn = 0; tn < NT; tn++) {
                int n = wn + tn*8 + g;
                bf[tn][0] = f2tf32(Bsb[n*SK + kb + tg]);
                bf[tn][1] = f2tf32(Bsb[n*SK + kb + tg + 4]);
            }
#pragma unroll
            for (int tm = 0; tm < MT; tm++) {
                int r = wm + tm*16 + g;
                uint32_t af[4];
                af[0] = f2tf32(Asb[(r    )*SK + kb + tg    ]);
                af[1] = f2tf32(Asb[(r + 8)*SK + kb + tg    ]);
                af[2] = f2tf32(Asb[(r    )*SK + kb + tg + 4]);
                af[3] = f2tf32(Asb[(r + 8)*SK + kb + tg + 4]);
#pragma unroll
                for (int tn = 0; tn < NT; tn++)
                    mma_tf32(acc[tm][tn], af, bf[tn]);
            }
        }
        __syncthreads();
    }

    // epilogue
#pragma unroll
    for (int tm = 0; tm < MT; tm++) {
        int mrow = m0 + wm + tm*16 + g;
#pragma unroll
        for (int tn = 0; tn < NT; tn++) {
            int ncol = n0 + wn + tn*8 + 2*tg;
            float b0v = 0.f, b1v = 0.f;
            if (HAS_BIAS) { b0v = bias[ncol]; b1v = bias[ncol+1]; }
            float v0 = acc[tm][tn][0] + b0v;
            float v1 = acc[tm][tn][1] + b1v;
            float v2 = acc[tm][tn][2] + b0v;
            float v3 = acc[tm][tn][3] + b1v;
            if (ACT == 1) {
                v0 = gelu_exact(v0); v1 = gelu_exact(v1);
                v2 = gelu_exact(v2); v3 = gelu_exact(v3);
            }
            size_t o0 = (size_t)mrow*ldc + ncol;
            size_t o1 = (size_t)(mrow+8)*ldc + ncol;
            if (HAS_RES) {
                float2 r0 = *reinterpret_cast<const float2*>(res + o0);
                float2 r1 = *reinterpret_cast<const float2*>(res + o1);
                v0 += r0.x; v1 += r0.y; v2 += r1.x; v3 += r1.y;
            }
            *reinterpret_cast<float2*>(C + o0) = make_float2(v0, v1);
            *reinterpret_cast<float2*>(C + o1) = make_float2(v2, v3);
        }
    }
}

// -------------------- fp32 SIMT GEMM (small/precision-critical) --------------------
template<int BN, int ACT, bool HAS_BIAS, bool HAS_RES, bool SPLIT>
__global__ __launch_bounds__(256) void gemm2(
    const float* __restrict__ A, int lda,
    const float* __restrict__ Bw, int ldb,
    const float* __restrict__ bias,
    const float* res,
    float* C, int ldc,
    int M, int N, int Kd, int kSlice,
    float* part)
{
    const int BM = 128, BK = 8, TM = 8;
    const int TN = BN / 16;
    __shared__ float As[2][BK][BM+4];
    __shared__ float Bs[2][BK][BN+4];

    int tid = threadIdx.x;
    int tx = tid & 15, ty = tid >> 4;
    int m0 = blockIdx.y * BM;
    int n0 = blockIdx.x * BN;
    int kBegin = SPLIT ? blockIdx.z * kSlice : 0;
    int kCount = SPLIT ? kSlice : Kd;

    float acc[TM][TN];
#pragma unroll
    for (int i = 0; i < TM; i++)
#pragma unroll
        for (int j = 0; j < TN; j++) acc[i][j] = 0.f;

    auto loadTiles = [&](int k0, int buf) {
        {
            int m = tid >> 1;
            int kv = (tid & 1) * 4;
            float4 v = *reinterpret_cast<const float4*>(A + (size_t)(m0+m)*lda + k0 + kv);
            As[buf][kv+0][m] = v.x; As[buf][kv+1][m] = v.y;
            As[buf][kv+2][m] = v.z; As[buf][kv+3][m] = v.w;
        }
#pragma unroll
        for (int f = tid; f < BN*BK/4; f += 256) {
            int n = f >> 1;
            int kv = (f & 1) * 4;
            float4 v = make_float4(0.f,0.f,0.f,0.f);
            if (n0 + n < N)
                v = *reinterpret_cast<const float4*>(Bw + (size_t)(n0+n)*ldb + k0 + kv);
            Bs[buf][kv+0][n] = v.x; Bs[buf][kv+1][n] = v.y;
            Bs[buf][kv+2][n] = v.z; Bs[buf][kv+3][n] = v.w;
        }
    };

    loadTiles(kBegin, 0);
    __syncthreads();

    int nIter = kCount / BK;
    for (int it = 0; it < nIter; it++) {
        int buf = it & 1;
        if (it + 1 < nIter) loadTiles(kBegin + (it+1)*BK, buf ^ 1);
#pragma unroll
        for (int k = 0; k < BK; k++) {
            float am[TM], bn[TN];
            {
                float4 a0 = *reinterpret_cast<const float4*>(&As[buf][k][ty*TM]);
                float4 a1 = *reinterpret_cast<const float4*>(&As[buf][k][ty*TM+4]);
                am[0]=a0.x; am[1]=a0.y; am[2]=a0.z; am[3]=a0.w;
                am[4]=a1.x; am[5]=a1.y; am[6]=a1.z; am[7]=a1.w;
            }
            if (TN == 8) {
                float4 b0 = *reinterpret_cast<const float4*>(&Bs[buf][k][tx*TN]);
                float4 b1 = *reinterpret_cast<const float4*>(&Bs[buf][k][tx*TN+4]);
                bn[0]=b0.x; bn[1]=b0.y; bn[2]=b0.z; bn[3]=b0.w;
                bn[4]=b1.x; bn[5]=b1.y; bn[6]=b1.z; bn[7]=b1.w;
            } else {
                float4 b0 = *reinterpret_cast<const float4*>(&Bs[buf][k][tx*TN]);
                bn[0]=b0.x; bn[1]=b0.y; bn[2]=b0.z; bn[3]=b0.w;
            }
#pragma unroll
            for (int i = 0; i < TM; i++)
#pragma unroll
                for (int j = 0; j < TN; j++)
                    acc[i][j] = fmaf(am[i], bn[j], acc[i][j]);
        }
        __syncthreads();
    }

    float* outp = SPLIT ? (part + (size_t)blockIdx.z * M * ldc) : C;
#pragma unroll
    for (int i = 0; i < TM; i++) {
        int m = m0 + ty*TM + i;
#pragma unroll
        for (int j = 0; j < TN; j++) {
            int n = n0 + tx*TN + j;
            if (n < N) {
                float v = acc[i][j];
                if (!SPLIT) {
                    if (HAS_BIAS) v += bias[n];
                    if (ACT == 1) v = gelu_exact(v);
                    else if (ACT == 2) v = (v > 20.f) ? v : log1pf(__expf(v));
                    if (HAS_RES) v += res[(size_t)m*ldc + n];
                }
                outp[(size_t)m*ldc + n] = v;
            }
        }
    }
}

// reduce split-K partials
__global__ void reduce_splitk(const float* __restrict__ part, float* __restrict__ out, int MN) {
    int i = blockIdx.x*256 + threadIdx.x;
    if (i >= MN) return;
    float s = 0.f;
#pragma unroll
    for (int k = 0; k < XSPLIT; k++) s += part[(size_t)k*MN + i];
    out[i] = s;
}

// -------------------- causal depthwise conv (K=4) + silu --------------------
__global__ void conv_silu_kernel(const float* __restrict__ xz,
                                 const float* __restrict__ cw,
                                 const float* __restrict__ cb,
                                 float* __restrict__ xc) {
    int idx = blockIdx.x * blockDim.x + threadIdx.x;
    if (idx >= RTOT*DII) return;
    int d = idx % DII;
    int r = idx / DII;
    int s = r & (SS-1);
    float acc = cb[d];
#pragma unroll
    for (int k = 0; k < KKC; k++) {
        int sk = s - (KKC-1) + k;
        if (sk >= 0)
            acc = fmaf(xz[(size_t)(r + sk - s)*(2*DII) + d], cw[d*KKC + k], acc);
    }
    float sg = 1.f / (1.f + __expf(-acc));
    xc[idx] = acc * sg;
}

// -------------------- selective scan (software-pipelined loads) --------------------
__global__ __launch_bounds__(128) void scan_kernel(
    const float* __restrict__ delta, const float* __restrict__ dbc,
    const float* __restrict__ xc,    const float* __restrict__ xz,
    const float* __restrict__ A_log, const float* __restrict__ Dw,
    float* __restrict__ y)
{
    int b = blockIdx.y;
    int d = blockIdx.x*128 + threadIdx.x;

    float Av[DSS];
#pragma unroll
    for (int i = 0; i < DSS; i++) Av[i] = -__expf(A_log[d*DSS + i]);
    float a0 = Av[0];
    bool fast = true;
#pragma unroll
    for (int i = 0; i < DSS; i++)
        if (fabsf(Av[i] - (float)(i+1)*a0) > 1e-4f*fabsf(Av[i]) + 1e-6f) fast = false;

    float Dd = Dw[d];
    float h[DSS];
#pragma unroll
    for (int i = 0; i < DSS; i++) h[i] = 0.f;

    __shared__ float sBC[32][33];

    size_t rBase = (size_t)b*SS;
    // prime pipeline with step 0
    float dl = delta[rBase*DII + d];
    float u  = xc[rBase*DII + d];
    float z  = xz[rBase*2*DII + DII + d];

    for (int s0 = 0; s0 < SS; s0 += 32) {
        __syncthreads();
#pragma unroll
        for (int q = 0; q < 8; q++) {
            int f = threadIdx.x + q*128;
            int j = f >> 5, c = f & 31;
            sBC[j][c] = dbc[(rBase + s0 + j)*DBCW + DTRR + c];
        }
        __syncthreads();
        for (int j = 0; j < 32; j++) {
            size_t r  = rBase + s0 + j;
            size_t rn = (s0 + j + 1 < SS) ? r + 1 : r;
            // prefetch next step (independent of the serial chain below)
            float dl_n = delta[rn*DII + d];
            float u_n  = xc[rn*DII + d];
            float z_n  = xz[rn*2*DII + DII + d];

            float du = dl*u;
            float yacc = 0.f;
            if (fast) {
                float t = __expf(dl*a0);
                float p = 1.f;
#pragma unroll
                for (int i = 0; i < DSS; i++) {
                    p *= t;
                    h[i] = fmaf(h[i], p, du*sBC[j][i]);
                    yacc = fmaf(h[i], sBC[j][16+i], yacc);
                }
            } else {
#pragma unroll
                for (int i = 0; i < DSS; i++) {
                    float e = __expf(dl*Av[i]);
                    h[i] = fmaf(h[i], e, du*sBC[j][i]);
                    yacc = fmaf(h[i], sBC[j][16+i], yacc);
                }
            }
            float ys = yacc + u*Dd;
            float sg = 1.f / (1.f + __expf(-z));
            y[r*DII + d] = ys * (z*sg);

            dl = dl_n; u = u_n; z = z_n;
        }
    }
}

// -------------------- final LN + head --------------------
__global__ __launch_bounds__(256) void headrow_kernel(const float* __restrict__ x,
                                                      const float* __restrict__ w,
                                                      const float* __restrict__ b,
                                                      const float* __restrict__ wh,
                                                      float* __restrict__ rowdot) {
    int row = blockIdx.x;
    const float* xr = x + (size_t)row*DMM;
    float v[3];
    float s = 0.f, sq = 0.f;
#pragma unroll
    for (int i = 0; i < 3; i++) {
        v[i] = xr[threadIdx.x + 256*i];
        s += v[i]; sq += v[i]*v[i];
    }
    __shared__ float sms[8], smq[8];
    __shared__ float mu_s, rs_s;
#pragma unroll
    for (int o = 16; o > 0; o >>= 1) {
        s  += __shfl_xor_sync(0xffffffffu, s,  o);
        sq += __shfl_xor_sync(0xffffffffu, sq, o);
    }
    int lane = threadIdx.x & 31, wid = threadIdx.x >> 5;
    if (lane == 0) { sms[wid] = s; smq[wid] = sq; }
    __syncthreads();
    if (threadIdx.x == 0) {
        float S = 0.f, Q = 0.f;
        for (int i = 0; i < 8; i++) { S += sms[i]; Q += smq[i]; }
        float mu = S * (1.0f/DMM);
        float var = Q * (1.0f/DMM) - mu*mu;
        mu_s = mu; rs_s = rsqrtf(var + 1e-5f);
    }
    __syncthreads();
    float mu = mu_s, rs = rs_s;
    float p = 0.f;
#pragma unroll
    for (int i = 0; i < 3; i++) {
        int d = threadIdx.x + 256*i;
        p = fmaf((v[i]-mu)*rs*w[d] + b[d], wh[d], p);
    }
#pragma unroll
    for (int o = 16; o > 0; o >>= 1) p += __shfl_xor_sync(0xffffffffu, p, o);
    __syncthreads();
    if (lane == 0) sms[wid] = p;
    __syncthreads();
    if (threadIdx.x == 0) {
        float S = 0.f;
        for (int i = 0; i < 8; i++) S += sms[i];
        rowdot[row] = S;
    }
}

__global__ __launch_bounds__(256) void final_kernel(const float* __restrict__ rowdot,
                                                    const float* __restrict__ b_head,
                                                    float* __restrict__ out) {
    int b = blockIdx.x;
    float s = 0.f;
    for (int j = threadIdx.x; j < SS; j += 256) s += rowdot[b*SS + j];
    __shared__ float sms[8];
#pragma unroll
    for (int o = 16; o > 0; o >>= 1) s += __shfl_xor_sync(0xffffffffu, s, o);
    int lane = threadIdx.x & 31, wid = threadIdx.x >> 5;
    if (lane == 0) sms[wid] = s;
    __syncthreads();
    if (threadIdx.x == 0) {
        float S = 0.f;
        for (int i = 0; i < 8; i++) S += sms[i];
        out[b] = b_head[0] + S * (1.0f/SS);
    }
}

// -------------------- launch --------------------
extern "C" void kernel_launch(void* const* d_in, const int* in_sizes, int n_in,
                              void* d_out, int out_size) {
    const float* x        = (const float*)d_in[0];
    const float* w_in     = (const float*)d_in[1];
    const float* b_in     = (const float*)d_in[2];
    const float* pe       = (const float*)d_in[3];
    const float* ln1_w    = (const float*)d_in[4];
    const float* ln1_b    = (const float*)d_in[5];
    const float* w_inproj = (const float*)d_in[6];
    const float* conv_w   = (const float*)d_in[7];
    const float* conv_b   = (const float*)d_in[8];
    const float* w_xproj  = (const float*)d_in[9];
    const float* w_dt     = (const float*)d_in[10];
    const float* b_dt     = (const float*)d_in[11];
    const float* A_log    = (const float*)d_in[12];
    const float* Dmat     = (const float*)d_in[13];
    const float* w_outproj= (const float*)d_in[14];
    const float* ln2_w    = (const float*)d_in[15];
    const float* ln2_b    = (const float*)d_in[16];
    const float* ff_w1    = (const float*)d_in[17];
    const float* ff_b1    = (const float*)d_in[18];
    const float* ff_w2    = (const float*)d_in[19];
    const float* ff_b2    = (const float*)d_in[20];
    const float* lnf_w    = (const float*)d_in[21];
    const float* lnf_b    = (const float*)d_in[22];
    const float* w_head   = (const float*)d_in[23];
    const float* b_head   = (const float*)d_in[24];
    float* out = (float*)d_out;

    float *h, *xln, *xz, *xc, *dbc, *delta, *y, *part, *rowdot;
    cudaGetSymbolAddress((void**)&h,     g_h);
    cudaGetSymbolAddress((void**)&xln,   g_xln);
    cudaGetSymbolAddress((void**)&xz,    g_xz);
    cudaGetSymbolAddress((void**)&xc,    g_xc);
    cudaGetSymbolAddress((void**)&dbc,   g_dbc);
    cudaGetSymbolAddress((void**)&delta, g_delta);
    cudaGetSymbolAddress((void**)&y,     g_y);
    cudaGetSymbolAddress((void**)&part,  g_part);
    cudaGetSymbolAddress((void**)&rowdot,g_rowdot);

    // dynamic smem sizes: 3 stages * (BM + BN) * 20 floats
    const int SM128 = 3*(128+128)*20*4;   // 61,440 B
    const int SM64  = 3*(128+64)*20*4;    // 46,080 B
    cudaFuncSetAttribute(gemm_tc<128,0,false,false>, cudaFuncAttributeMaxDynamicSharedMemorySize, SM128);
    cudaFuncSetAttribute(gemm_tc<128,1,true,false>,  cudaFuncAttributeMaxDynamicSharedMemorySize, SM128);
    cudaFuncSetAttribute(gemm_tc<64,0,false,true>,   cudaFuncAttributeMaxDynamicSharedMemorySize, SM64);
    cudaFuncSetAttribute(gemm_tc<64,0,true,true>,    cudaFuncAttributeMaxDynamicSharedMemorySize, SM64);

    const int GM = RTOT/128;  // 16 row-blocks

    embed_kernel<<<(RTOT*DMM + 255)/256, 256>>>(x, w_in, b_in, pe, h);

    for (int l = 0; l < LLN; l++) {
        // ln1
        ln_kernel<<<RTOT, 256>>>(h, ln1_w + l*DMM, ln1_b + l*DMM, xln);
        // inproj: xz[2048,3072] = xln @ w_inproj^T   (TC tf32)
        gemm_tc<128,0,false,false><<<dim3((2*DII)/128, GM), 256, SM128>>>(
            xln, DMM, w_inproj + (size_t)l*2*DII*DMM, DMM, nullptr, nullptr,
            xz, 2*DII, RTOT, 2*DII, DMM);
        // conv + silu
        conv_silu_kernel<<<(RTOT*DII + 255)/256, 256>>>(
            xz, conv_w + (size_t)l*DII*KKC, conv_b + l*DII, xc);
        // xproj (split-K, fp32): dbc[2048,80] = xc @ w_xproj^T
        gemm2<128,0,false,false,true><<<dim3(1, GM, XSPLIT), 256>>>(
            xc, DII, w_xproj + (size_t)l*DBCW*DII, DII, nullptr, nullptr,
            nullptr, DBCW, RTOT, DBCW, DII, DII/XSPLIT, part);
        reduce_splitk<<<(RTOT*DBCW + 255)/256, 256>>>(part, dbc, RTOT*DBCW);
        // delta = softplus(dbc[:, :48] @ w_dt^T + b_dt)   (fp32)
        gemm2<128,2,true,false,false><<<dim3(DII/128, GM), 256>>>(
            dbc, DBCW, w_dt + (size_t)l*DII*DTRR, DTRR, b_dt + l*DII, nullptr,
            delta, DII, RTOT, DII, DTRR, DTRR, nullptr);
        // scan -> y
        scan_kernel<<<dim3(DII/128, BB), 128>>>(
            delta, dbc, xc, xz, A_log + (size_t)l*DII*DSS, Dmat + l*DII, y);
        // h += y @ w_outproj^T   (TC tf32)
        gemm_tc<64,0,false,true><<<dim3(DMM/64, GM), 256, SM64>>>(
            y, DII, w_outproj + (size_t)l*DMM*DII, DII, nullptr, h,
            h, DMM, RTOT, DMM, DII);
        // ln2
        ln_kernel<<<RTOT, 256>>>(h, ln2_w + l*DMM, ln2_b + l*DMM, xln);
        // ff1: f = gelu(xln @ ff_w1^T + b1)   (TC tf32)
        gemm_tc<128,1,true,false><<<dim3((2*DMM)/128, GM), 256, SM128>>>(
            xln, DMM, ff_w1 + (size_t)l*2*DMM*DMM, DMM, ff_b1 + l*2*DMM, nullptr,
            y, 2*DMM, RTOT, 2*DMM, DMM);
        // h += f @ ff_w2^T + b2   (TC tf32)
        gemm_tc<64,0,true,true><<<dim3(DMM/64, GM), 256, SM64>>>(
            y, 2*DMM, ff_w2 + (size_t)l*DMM*2*DMM, 2*DMM, ff_b2 + l*DMM, h,
            h, DMM, RTOT, DMM, 2*DMM);
    }

    headrow_kernel<<<RTOT, 256>>>(h, lnf_w, lnf_b, w_head, rowdot);
    final_kernel<<<BB, 256>>>(rowdot, b_head, out);
}

// round 5
// speedup vs baseline: 2.6527x; 1.0861x over previous
#include <cuda_runtime.h>
#include <math.h>
#include <stdint.h>

#define BB   4
#define SS   512
#define DMM  768
#define LLN  2
#define DII  1536
#define DSS  16
#define KKC  4
#define DTRR 48
#define RTOT (BB*SS)         // 2048
#define DBCW (DTRR + 2*DSS)  // 80
#define XSPLIT 16            // split-K slices for xproj

// -------------------- scratch (device globals; no allocs) --------------------
__device__ float g_h    [RTOT*DMM];
__device__ float g_xln  [RTOT*DMM];
__device__ float g_xz   [RTOT*2*DII];
__device__ float g_xc   [RTOT*DII];
__device__ float g_dbc  [RTOT*DBCW];
__device__ float g_delta[RTOT*DII];
__device__ float g_y    [RTOT*DII];
__device__ float g_part [XSPLIT*RTOT*DBCW];
__device__ float g_rowdot[RTOT];

// -------------------- helpers --------------------
__device__ __forceinline__ void mma_tf32(float* c, const uint32_t* a, const uint32_t* b) {
    asm volatile(
        "mma.sync.aligned.m16n8k8.row.col.f32.tf32.tf32.f32 "
        "{%0,%1,%2,%3}, {%4,%5,%6,%7}, {%8,%9}, {%0,%1,%2,%3};"
        : "+f"(c[0]), "+f"(c[1]), "+f"(c[2]), "+f"(c[3])
        : "r"(a[0]), "r"(a[1]), "r"(a[2]), "r"(a[3]), "r"(b[0]), "r"(b[1]));
}
__device__ __forceinline__ void cp_async16(uint32_t smem_addr, const float* gptr) {
    asm volatile("cp.async.cg.shared.global [%0], [%1], 16;\n"
                 :: "r"(smem_addr), "l"(gptr));
}
__device__ __forceinline__ void cp_commit() {
    asm volatile("cp.async.commit_group;\n" ::: "memory");
}
template<int N>
__device__ __forceinline__ void cp_wait() {
    asm volatile("cp.async.wait_group %0;\n" :: "n"(N) : "memory");
}
__device__ __forceinline__ float gelu_exact(float v) {
    return 0.5f * v * (1.0f + erff(v * 0.70710678118654752f));
}

// -------------------- embed --------------------
__global__ void embed_kernel(const float* __restrict__ x, const float* __restrict__ w_in,
                             const float* __restrict__ b_in, const float* __restrict__ pe,
                             float* __restrict__ h) {
    int idx = blockIdx.x * blockDim.x + threadIdx.x;
    if (idx >= RTOT*DMM) return;
    int r = idx / DMM;
    int d = idx - r*DMM;
    int s = r & (SS-1);
    h[idx] = x[r]*w_in[d] + b_in[d] + pe[s*DMM + d];
}

// -------------------- layernorm --------------------
__global__ __launch_bounds__(256) void ln_kernel(const float* __restrict__ x,
                                                 const float* __restrict__ w,
                                                 const float* __restrict__ b,
                                                 float* __restrict__ y) {
    int row = blockIdx.x;
    const float* xr = x + (size_t)row*DMM;
    float v[3];
    float s = 0.f, sq = 0.f;
#pragma unroll
    for (int i = 0; i < 3; i++) {
        v[i] = xr[threadIdx.x + 256*i];
        s  += v[i];
        sq += v[i]*v[i];
    }
    __shared__ float sms[8], smq[8];
    __shared__ float mu_s, rs_s;
#pragma unroll
    for (int o = 16; o > 0; o >>= 1) {
        s  += __shfl_xor_sync(0xffffffffu, s,  o);
        sq += __shfl_xor_sync(0xffffffffu, sq, o);
    }
    int lane = threadIdx.x & 31, wid = threadIdx.x >> 5;
    if (lane == 0) { sms[wid] = s; smq[wid] = sq; }
    __syncthreads();
    if (threadIdx.x == 0) {
        float S = 0.f, Q = 0.f;
        for (int i = 0; i < 8; i++) { S += sms[i]; Q += smq[i]; }
        float mu = S * (1.0f/DMM);
        float var = Q * (1.0f/DMM) - mu*mu;
        mu_s = mu;
        rs_s = rsqrtf(var + 1e-5f);
    }
    __syncthreads();
    float mu = mu_s, rs = rs_s;
    float* yr = y + (size_t)row*DMM;
#pragma unroll
    for (int i = 0; i < 3; i++) {
        int d = threadIdx.x + 256*i;
        yr[d] = (v[i]-mu)*rs*w[d] + b[d];
    }
}

// -------------------- tensor-core tf32 GEMM, cp.async 4-stage, no-cvt --------------------
// C[M,N] = act(A[M,K] @ B[N,K]^T + bias) (+res)
// BM=128, BK=16/stage, 256 threads, dynamic smem, single sync per iter.
// Raw f32 bits fed to HMMA (HW truncates to tf32). ACT: 0 none, 1 gelu, 2 softplus.
// Requires: M%128==0, N%BN==0, K%16==0.
template<int BN, int ACT, bool HAS_BIAS, bool HAS_RES>
__global__ __launch_bounds__(256, 2) void gemm_tc(
    const float* __restrict__ A, int lda,
    const float* __restrict__ Bw, int ldb,     // (N, K) row-major
    const float* __restrict__ bias,
    const float* res,
    float* C, int ldc,
    int M, int N, int Kd)
{
    const int BM = 128, SK = 20, STG = 4;
    const int WC = (BN == 128) ? 4 : 2;          // warps along n
    const int WARP_M = (BN == 128) ? 64 : 32;
    const int WARP_N = 32;
    const int MT = WARP_M / 16;
    const int NT = WARP_N / 8;

    extern __shared__ float sm[];
    float* As = sm;                        // STG * BM * SK
    float* Bs = sm + STG*BM*SK;            // STG * BN * SK

    int tid  = threadIdx.x;
    int wid  = tid >> 5;
    int lane = tid & 31;
    int g    = lane >> 2;
    int tg   = lane & 3;
    int wm = (wid / WC) * WARP_M;
    int wn = (wid % WC) * WARP_N;
    int m0 = blockIdx.y * BM;
    int n0 = blockIdx.x * BN;

    float acc[MT][NT][4];
#pragma unroll
    for (int i = 0; i < MT; i++)
#pragma unroll
        for (int j = 0; j < NT; j++)
#pragma unroll
            for (int q = 0; q < 4; q++) acc[i][j][q] = 0.f;

    auto stageLoad = [&](int k0, int buf) {
        float* Asb = As + buf*BM*SK;
        float* Bsb = Bs + buf*BN*SK;
#pragma unroll
        for (int q = 0; q < 2; q++) {
            int f = tid + q*256;
            int m = f >> 2, kv = (f & 3) * 4;
            cp_async16((uint32_t)__cvta_generic_to_shared(Asb + m*SK + kv),
                       A + (size_t)(m0+m)*lda + k0 + kv);
        }
#pragma unroll
        for (int q = 0; q < BN/64; q++) {
            int f = tid + q*256;
            int n = f >> 2, kv = (f & 3) * 4;
            cp_async16((uint32_t)__cvta_generic_to_shared(Bsb + n*SK + kv),
                       Bw + (size_t)(n0+n)*ldb + k0 + kv);
        }
    };

    int nIter = Kd / 16;   // >= 3 at all call sites
    stageLoad(0, 0);  cp_commit();
    stageLoad(16, 1); cp_commit();
    stageLoad(32, 2); cp_commit();

    for (int it = 0; it < nIter; it++) {
        cp_wait<2>();
        __syncthreads();

        int buf = it & 3;
        const float* Asb = As + buf*BM*SK;
        const float* Bsb = Bs + buf*BN*SK;
#pragma unroll
        for (int kk = 0; kk < 2; kk++) {
            int kb = kk*8;
            uint32_t bf[NT][2];
#pragma unroll
            for (int tn = 0; tn < NT; tn++) {
                int n = wn + tn*8 + g;
                bf[tn][0] = __float_as_uint(Bsb[n*SK + kb + tg]);
                bf[tn][1] = __float_as_uint(Bsb[n*SK + kb + tg + 4]);
            }
#pragma unroll
            for (int tm = 0; tm < MT; tm++) {
                int r = wm + tm*16 + g;
                uint32_t af[4];
                af[0] = __float_as_uint(Asb[(r    )*SK + kb + tg    ]);
                af[1] = __float_as_uint(Asb[(r + 8)*SK + kb + tg    ]);
                af[2] = __float_as_uint(Asb[(r    )*SK + kb + tg + 4]);
                af[3] = __float_as_uint(Asb[(r + 8)*SK + kb + tg + 4]);
#pragma unroll
                for (int tn = 0; tn < NT; tn++)
                    mma_tf32(acc[tm][tn], af, bf[tn]);
            }
        }

        int nxt = it + 3;
        if (nxt < nIter) stageLoad(nxt*16, nxt & 3);
        cp_commit();
    }

    // epilogue
#pragma unroll
    for (int tm = 0; tm < MT; tm++) {
        int mrow = m0 + wm + tm*16 + g;
#pragma unroll
        for (int tn = 0; tn < NT; tn++) {
            int ncol = n0 + wn + tn*8 + 2*tg;
            float b0v = 0.f, b1v = 0.f;
            if (HAS_BIAS) { b0v = bias[ncol]; b1v = bias[ncol+1]; }
            float v0 = acc[tm][tn][0] + b0v;
            float v1 = acc[tm][tn][1] + b1v;
            float v2 = acc[tm][tn][2] + b0v;
            float v3 = acc[tm][tn][3] + b1v;
            if (ACT == 1) {
                v0 = gelu_exact(v0); v1 = gelu_exact(v1);
                v2 = gelu_exact(v2); v3 = gelu_exact(v3);
            } else if (ACT == 2) {
                v0 = (v0 > 20.f) ? v0 : log1pf(__expf(v0));
                v1 = (v1 > 20.f) ? v1 : log1pf(__expf(v1));
                v2 = (v2 > 20.f) ? v2 : log1pf(__expf(v2));
                v3 = (v3 > 20.f) ? v3 : log1pf(__expf(v3));
            }
            size_t o0 = (size_t)mrow*ldc + ncol;
            size_t o1 = (size_t)(mrow+8)*ldc + ncol;
            if (HAS_RES) {
                float2 r0 = *reinterpret_cast<const float2*>(res + o0);
                float2 r1 = *reinterpret_cast<const float2*>(res + o1);
                v0 += r0.x; v1 += r0.y; v2 += r1.x; v3 += r1.y;
            }
            *reinterpret_cast<float2*>(C + o0) = make_float2(v0, v1);
            *reinterpret_cast<float2*>(C + o1) = make_float2(v2, v3);
        }
    }
}

// -------------------- fp32 SIMT GEMM (xproj split-K) --------------------
template<int BN, int ACT, bool HAS_BIAS, bool HAS_RES, bool SPLIT>
__global__ __launch_bounds__(256) void gemm2(
    const float* __restrict__ A, int lda,
    const float* __restrict__ Bw, int ldb,
    const float* __restrict__ bias,
    const float* res,
    float* C, int ldc,
    int M, int N, int Kd, int kSlice,
    float* part)
{
    const int BM = 128, BK = 8, TM = 8;
    const int TN = BN / 16;
    __shared__ float As[2][BK][BM+4];
    __shared__ float Bs[2][BK][BN+4];

    int tid = threadIdx.x;
    int tx = tid & 15, ty = tid >> 4;
    int m0 = blockIdx.y * BM;
    int n0 = blockIdx.x * BN;
    int kBegin = SPLIT ? blockIdx.z * kSlice : 0;
    int kCount = SPLIT ? kSlice : Kd;

    float acc[TM][TN];
#pragma unroll
    for (int i = 0; i < TM; i++)
#pragma unroll
        for (int j = 0; j < TN; j++) acc[i][j] = 0.f;

    auto loadTiles = [&](int k0, int buf) {
        {
            int m = tid >> 1;
            int kv = (tid & 1) * 4;
            float4 v = *reinterpret_cast<const float4*>(A + (size_t)(m0+m)*lda + k0 + kv);
            As[buf][kv+0][m] = v.x; As[buf][kv+1][m] = v.y;
            As[buf][kv+2][m] = v.z; As[buf][kv+3][m] = v.w;
        }
#pragma unroll
        for (int f = tid; f < BN*BK/4; f += 256) {
            int n = f >> 1;
            int kv = (f & 1) * 4;
            float4 v = make_float4(0.f,0.f,0.f,0.f);
            if (n0 + n < N)
                v = *reinterpret_cast<const float4*>(Bw + (size_t)(n0+n)*ldb + k0 + kv);
            Bs[buf][kv+0][n] = v.x; Bs[buf][kv+1][n] = v.y;
            Bs[buf][kv+2][n] = v.z; Bs[buf][kv+3][n] = v.w;
        }
    };

    loadTiles(kBegin, 0);
    __syncthreads();

    int nIter = kCount / BK;
    for (int it = 0; it < nIter; it++) {
        int buf = it & 1;
        if (it + 1 < nIter) loadTiles(kBegin + (it+1)*BK, buf ^ 1);
#pragma unroll
        for (int k = 0; k < BK; k++) {
            float am[TM], bn[TN];
            {
                float4 a0 = *reinterpret_cast<const float4*>(&As[buf][k][ty*TM]);
                float4 a1 = *reinterpret_cast<const float4*>(&As[buf][k][ty*TM+4]);
                am[0]=a0.x; am[1]=a0.y; am[2]=a0.z; am[3]=a0.w;
                am[4]=a1.x; am[5]=a1.y; am[6]=a1.z; am[7]=a1.w;
            }
            if (TN == 8) {
                float4 b0 = *reinterpret_cast<const float4*>(&Bs[buf][k][tx*TN]);
                float4 b1 = *reinterpret_cast<const float4*>(&Bs[buf][k][tx*TN+4]);
                bn[0]=b0.x; bn[1]=b0.y; bn[2]=b0.z; bn[3]=b0.w;
                bn[4]=b1.x; bn[5]=b1.y; bn[6]=b1.z; bn[7]=b1.w;
            } else {
                float4 b0 = *reinterpret_cast<const float4*>(&Bs[buf][k][tx*TN]);
                bn[0]=b0.x; bn[1]=b0.y; bn[2]=b0.z; bn[3]=b0.w;
            }
#pragma unroll
            for (int i = 0; i < TM; i++)
#pragma unroll
                for (int j = 0; j < TN; j++)
                    acc[i][j] = fmaf(am[i], bn[j], acc[i][j]);
        }
        __syncthreads();
    }

    float* outp = SPLIT ? (part + (size_t)blockIdx.z * M * ldc) : C;
#pragma unroll
    for (int i = 0; i < TM; i++) {
        int m = m0 + ty*TM + i;
#pragma unroll
        for (int j = 0; j < TN; j++) {
            int n = n0 + tx*TN + j;
            if (n < N) {
                float v = acc[i][j];
                if (!SPLIT) {
                    if (HAS_BIAS) v += bias[n];
                    if (ACT == 1) v = gelu_exact(v);
                    else if (ACT == 2) v = (v > 20.f) ? v : log1pf(__expf(v));
                    if (HAS_RES) v += res[(size_t)m*ldc + n];
                }
                outp[(size_t)m*ldc + n] = v;
            }
        }
    }
}

// reduce split-K partials
__global__ void reduce_splitk(const float* __restrict__ part, float* __restrict__ out, int MN) {
    int i = blockIdx.x*256 + threadIdx.x;
    if (i >= MN) return;
    float s = 0.f;
#pragma unroll
    for (int k = 0; k < XSPLIT; k++) s += part[(size_t)k*MN + i];
    out[i] = s;
}

// -------------------- causal depthwise conv (K=4) + silu --------------------
__global__ void conv_silu_kernel(const float* __restrict__ xz,
                                 const float* __restrict__ cw,
                                 const float* __restrict__ cb,
                                 float* __restrict__ xc) {
    int idx = blockIdx.x * blockDim.x + threadIdx.x;
    if (idx >= RTOT*DII) return;
    int d = idx % DII;
    int r = idx / DII;
    int s = r & (SS-1);
    float acc = cb[d];
#pragma unroll
    for (int k = 0; k < KKC; k++) {
        int sk = s - (KKC-1) + k;
        if (sk >= 0)
            acc = fmaf(xz[(size_t)(r + sk - s)*(2*DII) + d], cw[d*KKC + k], acc);
    }
    float sg = 1.f / (1.f + __expf(-acc));
    xc[idx] = acc * sg;
}

// -------------------- selective scan (software-pipelined loads) --------------------
__global__ __launch_bounds__(128) void scan_kernel(
    const float* __restrict__ delta, const float* __restrict__ dbc,
    const float* __restrict__ xc,    const float* __restrict__ xz,
    const float* __restrict__ A_log, const float* __restrict__ Dw,
    float* __restrict__ y)
{
    int b = blockIdx.y;
    int d = blockIdx.x*128 + threadIdx.x;

    float Av[DSS];
#pragma unroll
    for (int i = 0; i < DSS; i++) Av[i] = -__expf(A_log[d*DSS + i]);
    float a0 = Av[0];
    bool fast = true;
#pragma unroll
    for (int i = 0; i < DSS; i++)
        if (fabsf(Av[i] - (float)(i+1)*a0) > 1e-4f*fabsf(Av[i]) + 1e-6f) fast = false;

    float Dd = Dw[d];
    float h[DSS];
#pragma unroll
    for (int i = 0; i < DSS; i++) h[i] = 0.f;

    __shared__ float sBC[32][33];

    size_t rBase = (size_t)b*SS;
    float dl = delta[rBase*DII + d];
    float u  = xc[rBase*DII + d];
    float z  = xz[rBase*2*DII + DII + d];

    for (int s0 = 0; s0 < SS; s0 += 32) {
        __syncthreads();
#pragma unroll
        for (int q = 0; q < 8; q++) {
            int f = threadIdx.x + q*128;
            int j = f >> 5, c = f & 31;
            sBC[j][c] = dbc[(rBase + s0 + j)*DBCW + DTRR + c];
        }
        __syncthreads();
        for (int j = 0; j < 32; j++) {
            size_t r  = rBase + s0 + j;
            size_t rn = (s0 + j + 1 < SS) ? r + 1 : r;
            float dl_n = delta[rn*DII + d];
            float u_n  = xc[rn*DII + d];
            float z_n  = xz[rn*2*DII + DII + d];

            float du = dl*u;
            float yacc = 0.f;
            if (fast) {
                float t = __expf(dl*a0);
                float p = 1.f;
#pragma unroll
                for (int i = 0; i < DSS; i++) {
                    p *= t;
                    h[i] = fmaf(h[i], p, du*sBC[j][i]);
                    yacc = fmaf(h[i], sBC[j][16+i], yacc);
                }
            } else {
#pragma unroll
                for (int i = 0; i < DSS; i++) {
                    float e = __expf(dl*Av[i]);
                    h[i] = fmaf(h[i], e, du*sBC[j][i]);
                    yacc = fmaf(h[i], sBC[j][16+i], yacc);
                }
            }
            float ys = yacc + u*Dd;
            float sg = 1.f / (1.f + __expf(-z));
            y[r*DII + d] = ys * (z*sg);

            dl = dl_n; u = u_n; z = z_n;
        }
    }
}

// -------------------- final LN + head --------------------
__global__ __launch_bounds__(256) void headrow_kernel(const float* __restrict__ x,
                                                      const float* __restrict__ w,
                                                      const float* __restrict__ b,
                                                      const float* __restrict__ wh,
                                                      float* __restrict__ rowdot) {
    int row = blockIdx.x;
    const float* xr = x + (size_t)row*DMM;
    float v[3];
    float s = 0.f, sq = 0.f;
#pragma unroll
    for (int i = 0; i < 3; i++) {
        v[i] = xr[threadIdx.x + 256*i];
        s += v[i]; sq += v[i]*v[i];
    }
    __shared__ float sms[8], smq[8];
    __shared__ float mu_s, rs_s;
#pragma unroll
    for (int o = 16; o > 0; o >>= 1) {
        s  += __shfl_xor_sync(0xffffffffu, s,  o);
        sq += __shfl_xor_sync(0xffffffffu, sq, o);
    }
    int lane = threadIdx.x & 31, wid = threadIdx.x >> 5;
    if (lane == 0) { sms[wid] = s; smq[wid] = sq; }
    __syncthreads();
    if (threadIdx.x == 0) {
        float S = 0.f, Q = 0.f;
        for (int i = 0; i < 8; i++) { S += sms[i]; Q += smq[i]; }
        float mu = S * (1.0f/DMM);
        float var = Q * (1.0f/DMM) - mu*mu;
        mu_s = mu; rs_s = rsqrtf(var + 1e-5f);
    }
    __syncthreads();
    float mu = mu_s, rs = rs_s;
    float p = 0.f;
#pragma unroll
    for (int i = 0; i < 3; i++) {
        int d = threadIdx.x + 256*i;
        p = fmaf((v[i]-mu)*rs*w[d] + b[d], wh[d], p);
    }
#pragma unroll
    for (int o = 16; o > 0; o >>= 1) p += __shfl_xor_sync(0xffffffffu, p, o);
    __syncthreads();
    if (lane == 0) sms[wid] = p;
    __syncthreads();
    if (threadIdx.x == 0) {
        float S = 0.f;
        for (int i = 0; i < 8; i++) S += sms[i];
        rowdot[row] = S;
    }
}

__global__ __launch_bounds__(256) void final_kernel(const float* __restrict__ rowdot,
                                                    const float* __restrict__ b_head,
                                                    float* __restrict__ out) {
    int b = blockIdx.x;
    float s = 0.f;
    for (int j = threadIdx.x; j < SS; j += 256) s += rowdot[b*SS + j];
    __shared__ float sms[8];
#pragma unroll
    for (int o = 16; o > 0; o >>= 1) s += __shfl_xor_sync(0xffffffffu, s, o);
    int lane = threadIdx.x & 31, wid = threadIdx.x >> 5;
    if (lane == 0) sms[wid] = s;
    __syncthreads();
    if (threadIdx.x == 0) {
        float S = 0.f;
        for (int i = 0; i < 8; i++) S += sms[i];
        out[b] = b_head[0] + S * (1.0f/SS);
    }
}

// -------------------- launch --------------------
extern "C" void kernel_launch(void* const* d_in, const int* in_sizes, int n_in,
                              void* d_out, int out_size) {
    const float* x        = (const float*)d_in[0];
    const float* w_in     = (const float*)d_in[1];
    const float* b_in     = (const float*)d_in[2];
    const float* pe       = (const float*)d_in[3];
    const float* ln1_w    = (const float*)d_in[4];
    const float* ln1_b    = (const float*)d_in[5];
    const float* w_inproj = (const float*)d_in[6];
    const float* conv_w   = (const float*)d_in[7];
    const float* conv_b   = (const float*)d_in[8];
    const float* w_xproj  = (const float*)d_in[9];
    const float* w_dt     = (const float*)d_in[10];
    const float* b_dt     = (const float*)d_in[11];
    const float* A_log    = (const float*)d_in[12];
    const float* Dmat     = (const float*)d_in[13];
    const float* w_outproj= (const float*)d_in[14];
    const float* ln2_w    = (const float*)d_in[15];
    const float* ln2_b    = (const float*)d_in[16];
    const float* ff_w1    = (const float*)d_in[17];
    const float* ff_b1    = (const float*)d_in[18];
    const float* ff_w2    = (const float*)d_in[19];
    const float* ff_b2    = (const float*)d_in[20];
    const float* lnf_w    = (const float*)d_in[21];
    const float* lnf_b    = (const float*)d_in[22];
    const float* w_head   = (const float*)d_in[23];
    const float* b_head   = (const float*)d_in[24];
    float* out = (float*)d_out;

    float *h, *xln, *xz, *xc, *dbc, *delta, *y, *part, *rowdot;
    cudaGetSymbolAddress((void**)&h,     g_h);
    cudaGetSymbolAddress((void**)&xln,   g_xln);
    cudaGetSymbolAddress((void**)&xz,    g_xz);
    cudaGetSymbolAddress((void**)&xc,    g_xc);
    cudaGetSymbolAddress((void**)&dbc,   g_dbc);
    cudaGetSymbolAddress((void**)&delta, g_delta);
    cudaGetSymbolAddress((void**)&y,     g_y);
    cudaGetSymbolAddress((void**)&part,  g_part);
    cudaGetSymbolAddress((void**)&rowdot,g_rowdot);

    // dynamic smem: 4 stages * (BM + BN) * 20 floats
    const int SM128 = 4*(128+128)*20*4;   // 81,920 B
    const int SM64  = 4*(128+64)*20*4;    // 61,440 B
    cudaFuncSetAttribute(gemm_tc<128,0,false,false>, cudaFuncAttributeMaxDynamicSharedMemorySize, SM128);
    cudaFuncSetAttribute(gemm_tc<128,1,true,false>,  cudaFuncAttributeMaxDynamicSharedMemorySize, SM128);
    cudaFuncSetAttribute(gemm_tc<128,2,true,false>,  cudaFuncAttributeMaxDynamicSharedMemorySize, SM128);
    cudaFuncSetAttribute(gemm_tc<64,0,false,true>,   cudaFuncAttributeMaxDynamicSharedMemorySize, SM64);
    cudaFuncSetAttribute(gemm_tc<64,0,true,true>,    cudaFuncAttributeMaxDynamicSharedMemorySize, SM64);

    const int GM = RTOT/128;  // 16 row-blocks

    embed_kernel<<<(RTOT*DMM + 255)/256, 256>>>(x, w_in, b_in, pe, h);

    for (int l = 0; l < LLN; l++) {
        // ln1
        ln_kernel<<<RTOT, 256>>>(h, ln1_w + l*DMM, ln1_b + l*DMM, xln);
        // inproj: xz[2048,3072] = xln @ w_inproj^T   (TC tf32)
        gemm_tc<128,0,false,false><<<dim3((2*DII)/128, GM), 256, SM128>>>(
            xln, DMM, w_inproj + (size_t)l*2*DII*DMM, DMM, nullptr, nullptr,
            xz, 2*DII, RTOT, 2*DII, DMM);
        // conv + silu
        conv_silu_kernel<<<(RTOT*DII + 255)/256, 256>>>(
            xz, conv_w + (size_t)l*DII*KKC, conv_b + l*DII, xc);
        // xproj (split-K, fp32): dbc[2048,80] = xc @ w_xproj^T
        gemm2<128,0,false,false,true><<<dim3(1, GM, XSPLIT), 256>>>(
            xc, DII, w_xproj + (size_t)l*DBCW*DII, DII, nullptr, nullptr,
            nullptr, DBCW, RTOT, DBCW, DII, DII/XSPLIT, part);
        reduce_splitk<<<(RTOT*DBCW + 255)/256, 256>>>(part, dbc, RTOT*DBCW);
        // delta = softplus(dbc[:, :48] @ w_dt^T + b_dt)   (TC tf32, K=48)
        gemm_tc<128,2,true,false><<<dim3(DII/128, GM), 256, SM128>>>(
            dbc, DBCW, w_dt + (size_t)l*DII*DTRR, DTRR, b_dt + l*DII, nullptr,
            delta, DII, RTOT, DII, DTRR);
        // scan -> y
        scan_kernel<<<dim3(DII/128, BB), 128>>>(
            delta, dbc, xc, xz, A_log + (size_t)l*DII*DSS, Dmat + l*DII, y);
        // h += y @ w_outproj^T   (TC tf32)
        gemm_tc<64,0,false,true><<<dim3(DMM/64, GM), 256, SM64>>>(
            y, DII, w_outproj + (size_t)l*DMM*DII, DII, nullptr, h,
            h, DMM, RTOT, DMM, DII);
        // ln2
        ln_kernel<<<RTOT, 256>>>(h, ln2_w + l*DMM, ln2_b + l*DMM, xln);
        // ff1: f = gelu(xln @ ff_w1^T + b1)   (TC tf32)
        gemm_tc<128,1,true,false><<<dim3((2*DMM)/128, GM), 256, SM128>>>(
            xln, DMM, ff_w1 + (size_t)l*2*DMM*DMM, DMM, ff_b1 + l*2*DMM, nullptr,
            y, 2*DMM, RTOT, 2*DMM, DMM);
        // h += f @ ff_w2^T + b2   (TC tf32)
        gemm_tc<64,0,true,true><<<dim3(DMM/64, GM), 256, SM64>>>(
            y, 2*DMM, ff_w2 + (size_t)l*DMM*2*DMM, 2*DMM, ff_b2 + l*DMM, h,
            h, DMM, RTOT, DMM, 2*DMM);
    }

    headrow_kernel<<<RTOT, 256>>>(h, lnf_w, lnf_b, w_head, rowdot);
    final_kernel<<<BB, 256>>>(rowdot, b_head, out);
}